// round 2
// baseline (speedup 1.0000x reference)
#include <cuda_runtime.h>
#include <cuda_bf16.h>
#include <math.h>
#include <float.h>

// Problem constants
#define BB 2
#define LL 1024
#define TXT 1024
#define HID 2048
#define INTD 6144
#define NH 16
#define NKV 8
#define HD 128
#define NLAYERS 8
#define SW 128
#define EPSF 1e-6f
#define NTOK (BB*LL)          // 2048
#define ATT_SCALE 0.08838834764831845f  // 1/sqrt(128)

// ---------------- scratch (device globals; no allocation allowed) ----------
__device__ float g_h [NTOK*HID];        // 16 MB residual stream
__device__ float g_hn[NTOK*HID];        // normed
__device__ float g_q [NTOK*NH*HD];      // 16 MB
__device__ float g_k [NTOK*NKV*HD];     // 8 MB
__device__ float g_v [NTOK*NKV*HD];     // 8 MB
__device__ float g_s [(size_t)BB*NH*LL*LL]; // 128 MB scores
__device__ float g_o [NTOK*NH*HD];      // 16 MB
__device__ float g_g [NTOK*INTD];       // 48 MB
__device__ float g_u [NTOK*INTD];       // 48 MB
__device__ float g_cos[LL*HD];
__device__ float g_sin[LL*HD];

// ---------------- block reductions -----------------------------------------
__device__ __forceinline__ float blk_sum(float v) {
    __shared__ float s[8];
    #pragma unroll
    for (int o = 16; o; o >>= 1) v += __shfl_xor_sync(0xffffffffu, v, o);
    if ((threadIdx.x & 31) == 0) s[threadIdx.x >> 5] = v;
    __syncthreads();
    float t = 0.f;
    int nw = blockDim.x >> 5;
    #pragma unroll
    for (int i = 0; i < 8; i++) if (i < nw) t += s[i];
    __syncthreads();
    return t;
}

__device__ __forceinline__ float blk_max(float v) {
    __shared__ float s[8];
    #pragma unroll
    for (int o = 16; o; o >>= 1) v = fmaxf(v, __shfl_xor_sync(0xffffffffu, v, o));
    if ((threadIdx.x & 31) == 0) s[threadIdx.x >> 5] = v;
    __syncthreads();
    float t = -FLT_MAX;
    int nw = blockDim.x >> 5;
    #pragma unroll
    for (int i = 0; i < 8; i++) if (i < nw) t = fmaxf(t, s[i]);
    __syncthreads();
    return t;
}

// ---------------- generic 128x128x16 SGEMM body -----------------------------
// C[M,N] = (ACCUM? C : 0) + A[M,K] @ (TRANSB? B[N,K]^T : B[K,N]) (+ bias[n])
// All of M,N multiples of 128; K multiple of 16; all pointers 16B aligned.
#define BM 128
#define BN 128
#define BKC 16

template<bool TRANSB, bool ACCUM, bool BIAS>
__device__ __forceinline__ void gemm_dev(
    const float* __restrict__ A, const float* __restrict__ B,
    const float* __restrict__ bias, float* __restrict__ C,
    int K, int lda, int ldb, int ldc)
{
    __shared__ float As[BKC][BM + 4];
    __shared__ float Bs[BKC][BN + 4];

    const int bm = blockIdx.y * BM;
    const int bn = blockIdx.x * BN;
    const int tid = threadIdx.x;           // 256 threads
    const int tx = tid & 15;               // 0..15  (n groups of 8)
    const int ty = tid >> 4;               // 0..15  (m groups of 8)

    const int a_m = tid >> 2;              // 0..63 (+64)
    const int a_k = (tid & 3) * 4;

    float acc[8][8];
    #pragma unroll
    for (int i = 0; i < 8; i++)
        #pragma unroll
        for (int j = 0; j < 8; j++) acc[i][j] = 0.f;

    for (int k0 = 0; k0 < K; k0 += BKC) {
        // load A tile (store transposed)
        #pragma unroll
        for (int r = 0; r < 2; r++) {
            int m = a_m + r * 64;
            float4 val = *(const float4*)(A + (long long)(bm + m) * lda + k0 + a_k);
            As[a_k + 0][m] = val.x; As[a_k + 1][m] = val.y;
            As[a_k + 2][m] = val.z; As[a_k + 3][m] = val.w;
        }
        if (!TRANSB) {
            int b_kr = tid >> 5;           // 0..7 (+8)
            int b_n  = (tid & 31) * 4;
            #pragma unroll
            for (int r = 0; r < 2; r++) {
                int kk = b_kr + r * 8;
                float4 val = *(const float4*)(B + (long long)(k0 + kk) * ldb + bn + b_n);
                *(float4*)&Bs[kk][b_n] = val;
            }
        } else {
            #pragma unroll
            for (int r = 0; r < 2; r++) {
                int n = (tid >> 2) + r * 64;
                int kk = (tid & 3) * 4;
                float4 val = *(const float4*)(B + (long long)(bn + n) * ldb + k0 + kk);
                Bs[kk + 0][n] = val.x; Bs[kk + 1][n] = val.y;
                Bs[kk + 2][n] = val.z; Bs[kk + 3][n] = val.w;
            }
        }
        __syncthreads();

        #pragma unroll
        for (int kk = 0; kk < BKC; kk++) {
            float a[8], b[8];
            *(float4*)&a[0] = *(const float4*)&As[kk][ty * 8];
            *(float4*)&a[4] = *(const float4*)&As[kk][ty * 8 + 4];
            *(float4*)&b[0] = *(const float4*)&Bs[kk][tx * 8];
            *(float4*)&b[4] = *(const float4*)&Bs[kk][tx * 8 + 4];
            #pragma unroll
            for (int i = 0; i < 8; i++)
                #pragma unroll
                for (int j = 0; j < 8; j++)
                    acc[i][j] = fmaf(a[i], b[j], acc[i][j]);
        }
        __syncthreads();
    }

    // epilogue
    #pragma unroll
    for (int i = 0; i < 8; i++) {
        long long m = bm + ty * 8 + i;
        #pragma unroll
        for (int j = 0; j < 8; j += 4) {
            int n = bn + tx * 8 + j;
            float4 r;
            r.x = acc[i][j]; r.y = acc[i][j+1]; r.z = acc[i][j+2]; r.w = acc[i][j+3];
            if (BIAS) {
                r.x += bias[n]; r.y += bias[n+1]; r.z += bias[n+2]; r.w += bias[n+3];
            }
            if (ACCUM) {
                float4 c = *(const float4*)(C + m * ldc + n);
                r.x += c.x; r.y += c.y; r.z += c.z; r.w += c.w;
            }
            *(float4*)(C + m * ldc + n) = r;
        }
    }
}

__global__ void __launch_bounds__(256) gemm_nn(
    const float* A, const float* B, float* C, int K, int lda, int ldb, int ldc) {
    gemm_dev<false, false, false>(A, B, nullptr, C, K, lda, ldb, ldc);
}
__global__ void __launch_bounds__(256) gemm_nn_bias(
    const float* A, const float* B, const float* bias, float* C, int K, int lda, int ldb, int ldc) {
    gemm_dev<false, false, true>(A, B, bias, C, K, lda, ldb, ldc);
}
__global__ void __launch_bounds__(256) gemm_nn_acc(
    const float* A, const float* B, float* C, int K, int lda, int ldb, int ldc) {
    gemm_dev<false, true, false>(A, B, nullptr, C, K, lda, ldb, ldc);
}

// QK^T per (b,h): S[L,L] = Q_h[L,HD] @ K_kvh[L,HD]^T
__global__ void __launch_bounds__(256) qk_gemm() {
    int z = blockIdx.z;                    // 0..B*NH-1
    int b = z >> 4, h = z & 15, kvh = h >> 1;
    const float* A = g_q + ((long long)b * LL * NH + h) * HD;
    const float* B = g_k + ((long long)b * LL * NKV + kvh) * HD;
    float* C = g_s + (long long)z * LL * LL;
    gemm_dev<true, false, false>(A, B, nullptr, C, HD, NH * HD, NKV * HD, LL);
}

// AV per (b,h): O_h[L,HD] = P[L,L] @ V_kvh[L,HD]
__global__ void __launch_bounds__(256) av_gemm() {
    int z = blockIdx.z;
    int b = z >> 4, h = z & 15, kvh = h >> 1;
    const float* A = g_s + (long long)z * LL * LL;
    const float* B = g_v + ((long long)b * LL * NKV + kvh) * HD;
    float* C = g_o + ((long long)b * LL * NH + h) * HD;
    gemm_dev<false, false, false>(A, B, nullptr, C, LL, LL, NKV * HD, NH * HD);
}

// ---------------- RMSNorm over last dim D ----------------------------------
__global__ void rmsnorm_k(const float* __restrict__ X, const float* __restrict__ w,
                          float* __restrict__ Y, int D) {
    long long row = blockIdx.x;
    const float* x = X + row * D;
    float* y = Y + row * D;
    float ss = 0.f;
    for (int j = threadIdx.x; j < D; j += blockDim.x) { float v = x[j]; ss += v * v; }
    float tot = blk_sum(ss);
    float r = rsqrtf(tot / (float)D + EPSF);
    for (int j = threadIdx.x; j < D; j += blockDim.x) y[j] = w[j] * x[j] * r;
}

// ---------------- RoPE table (computed in double; fast-math safe) ----------
__global__ void rope_table_k() {
    int pos = blockIdx.x;
    int d = threadIdx.x;        // 0..127
    int j = d & 63;
    double inv = exp2(-(double)j * (19.931568569324174 / 64.0)); // 1e6^(-j/64)
    double ang = (double)pos * inv;
    g_cos[pos * HD + d] = (float)cos(ang);
    g_sin[pos * HD + d] = (float)sin(ang);
}

// ---------------- per-head RMSNorm + RoPE (in place on q/k) ----------------
__global__ void qknorm_rope_k(const float* __restrict__ wq, const float* __restrict__ wk) {
    int tok = blockIdx.x;                 // 0..NTOK-1
    int head = blockIdx.y;                // 0..NH+NKV-1
    int d = threadIdx.x;                  // 0..127
    float* base;
    const float* w;
    if (head < NH) { base = g_q + ((long long)tok * NH + head) * HD; w = wq; }
    else           { base = g_k + ((long long)tok * NKV + (head - NH)) * HD; w = wk; }

    float v = base[d];
    float ss = v * v;
    #pragma unroll
    for (int o = 16; o; o >>= 1) ss += __shfl_xor_sync(0xffffffffu, ss, o);
    __shared__ float wsum[4];
    __shared__ float sm[HD];
    if ((d & 31) == 0) wsum[d >> 5] = ss;
    __syncthreads();
    float tot = wsum[0] + wsum[1] + wsum[2] + wsum[3];
    float r = rsqrtf(tot / (float)HD + EPSF);
    float xn = w[d] * v * r;
    sm[d] = xn;
    __syncthreads();
    int pos = tok & (LL - 1);
    float c = g_cos[pos * HD + d];
    float s = g_sin[pos * HD + d];
    float rot = (d < 64) ? -sm[d + 64] : sm[d - 64];
    base[d] = xn * c + rot * s;
}

// ---------------- masked softmax over rows of S -----------------------------
__global__ void softmax_k(const int* __restrict__ amask, int sliding) {
    long long row = blockIdx.x;           // (b*NH + h)*L + q
    int b = (int)(row / ((long long)NH * LL));
    int q = (int)(row & (LL - 1));
    float* p = g_s + row * LL;
    int tid = threadIdx.x;

    float vals[4];
    float mx = -FLT_MAX;
    #pragma unroll
    for (int t = 0; t < 4; t++) {
        int k = tid + t * 256;
        bool keep = (amask[b * LL + k] != 0);
        if (sliding) keep = keep && (abs(q - k) <= SW);
        float v = keep ? p[k] * ATT_SCALE : -FLT_MAX;
        vals[t] = v;
        mx = fmaxf(mx, v);
    }
    mx = blk_max(mx);
    float sum = 0.f;
    #pragma unroll
    for (int t = 0; t < 4; t++) { vals[t] = expf(vals[t] - mx); sum += vals[t]; }
    sum = blk_sum(sum);
    float inv = 1.0f / sum;
    #pragma unroll
    for (int t = 0; t < 4; t++) p[tid + t * 256] = vals[t] * inv;
}

// ---------------- SiLU(g)*u -> g -------------------------------------------
__global__ void silu_mul_k(int n) {
    int i = blockIdx.x * blockDim.x + threadIdx.x;
    if (i < n) {
        float x = g_g[i];
        float s = x / (1.0f + expf(-x));
        g_g[i] = s * g_u[i];
    }
}

// ---------------- host orchestration ----------------------------------------
extern "C" void kernel_launch(void* const* d_in, const int* in_sizes, int n_in,
                              void* d_out, int out_size) {
    (void)in_sizes; (void)n_in; (void)out_size;
    const float* x       = (const float*)d_in[0];
    const int*   amask   = (const int*)  d_in[1];
    const float* W_embed = (const float*)d_in[2];
    const float* b_embed = (const float*)d_in[3];
    const float* Wq      = (const float*)d_in[4];
    const float* Wk      = (const float*)d_in[5];
    const float* Wv      = (const float*)d_in[6];
    const float* Wo      = (const float*)d_in[7];
    const float* w_in    = (const float*)d_in[8];
    const float* w_post  = (const float*)d_in[9];
    const float* w_qn    = (const float*)d_in[10];
    const float* w_kn    = (const float*)d_in[11];
    const float* Wg      = (const float*)d_in[12];
    const float* Wu      = (const float*)d_in[13];
    const float* Wd      = (const float*)d_in[14];
    const float* w_final = (const float*)d_in[15];

    float *h, *hn, *gbuf;
    cudaGetSymbolAddress((void**)&h,  g_h);
    cudaGetSymbolAddress((void**)&hn, g_hn);
    cudaGetSymbolAddress((void**)&gbuf, g_g);
    float *qb, *kb, *vb, *ob, *ub;
    cudaGetSymbolAddress((void**)&qb, g_q);
    cudaGetSymbolAddress((void**)&kb, g_k);
    cudaGetSymbolAddress((void**)&vb, g_v);
    cudaGetSymbolAddress((void**)&ob, g_o);
    cudaGetSymbolAddress((void**)&ub, g_u);

    // rope tables (same for every layer)
    rope_table_k<<<LL, HD>>>();

    // embed: h = x @ W_embed + b
    gemm_nn_bias<<<dim3(HID / BN, NTOK / BM), 256>>>(x, W_embed, b_embed, h, TXT, TXT, HID, HID);

    for (int i = 0; i < NLAYERS; i++) {
        rmsnorm_k<<<NTOK, 256>>>(h, w_in + (long long)i * HID, hn, HID);

        gemm_nn<<<dim3((NH*HD) / BN, NTOK / BM), 256>>>(
            hn, Wq + (long long)i * HID * NH * HD, qb, HID, HID, NH * HD, NH * HD);
        gemm_nn<<<dim3((NKV*HD) / BN, NTOK / BM), 256>>>(
            hn, Wk + (long long)i * HID * NKV * HD, kb, HID, HID, NKV * HD, NKV * HD);
        gemm_nn<<<dim3((NKV*HD) / BN, NTOK / BM), 256>>>(
            hn, Wv + (long long)i * HID * NKV * HD, vb, HID, HID, NKV * HD, NKV * HD);

        qknorm_rope_k<<<dim3(NTOK, NH + NKV), HD>>>(
            w_qn + (long long)i * HD, w_kn + (long long)i * HD);

        qk_gemm<<<dim3(LL / BN, LL / BM, BB * NH), 256>>>();
        softmax_k<<<(long long)BB * NH * LL, 256>>>(amask, (i % 2 == 0) ? 1 : 0);
        av_gemm<<<dim3(HD / BN, LL / BM, BB * NH), 256>>>();

        // h += o @ Wo
        gemm_nn_acc<<<dim3(HID / BN, NTOK / BM), 256>>>(
            ob, Wo + (long long)i * NH * HD * HID, h, NH * HD, NH * HD, HID, HID);

        rmsnorm_k<<<NTOK, 256>>>(h, w_post + (long long)i * HID, hn, HID);

        gemm_nn<<<dim3(INTD / BN, NTOK / BM), 256>>>(
            hn, Wg + (long long)i * HID * INTD, gbuf, HID, HID, INTD, INTD);
        gemm_nn<<<dim3(INTD / BN, NTOK / BM), 256>>>(
            hn, Wu + (long long)i * HID * INTD, ub, HID, HID, INTD, INTD);

        int nsm = NTOK * INTD;
        silu_mul_k<<<(nsm + 255) / 256, 256>>>(nsm);

        // h += act @ Wd
        gemm_nn_acc<<<dim3(HID / BN, NTOK / BM), 256>>>(
            gbuf, Wd + (long long)i * INTD * HID, h, INTD, INTD, HID, HID);
    }

    rmsnorm_k<<<NTOK, 256>>>(h, w_final, (float*)d_out, HID);
}

// round 3
// speedup vs baseline: 2.2727x; 2.2727x over previous
#include <cuda_runtime.h>
#include <cuda_bf16.h>
#include <math.h>
#include <float.h>
#include <stdint.h>

// Problem constants
#define BB 2
#define LL 1024
#define TXT 1024
#define HID 2048
#define INTD 6144
#define NH 16
#define NKV 8
#define HD 128
#define NLAYERS 8
#define SW 128
#define EPSF 1e-6f
#define NTOK (BB*LL)          // 2048
#define ATT_SCALE 0.08838834764831845f  // 1/sqrt(128)

// ---------------- scratch (device globals; no allocation allowed) ----------
__device__ float g_h [NTOK*HID];
__device__ float g_q [NTOK*NH*HD];
__device__ float g_k [NTOK*NKV*HD];
__device__ float g_v [NTOK*NKV*HD];
__device__ float g_s [(size_t)BB*NH*LL*LL]; // 128 MB scores
__device__ float g_o [NTOK*NH*HD];
__device__ float g_g [NTOK*INTD];
__device__ float g_u [NTOK*INTD];
__device__ float g_cos[LL*HD];
__device__ float g_sin[LL*HD];

// bf16 hi/lo splits
#define NWELEM 404750336LL   // all weights incl. embed
__device__ __nv_bfloat16 g_whi[NWELEM];
__device__ __nv_bfloat16 g_wlo[NWELEM];
__device__ __nv_bfloat16 g_hn_hi[NTOK*HID];
__device__ __nv_bfloat16 g_hn_lo[NTOK*HID];
__device__ __nv_bfloat16 g_act_hi[NTOK*INTD];
__device__ __nv_bfloat16 g_act_lo[NTOK*INTD];

// weight offsets inside g_whi/g_wlo
#define OFF_EMB 0LL
#define OFF_WQ  2097152LL
#define OFF_WK  35651584LL
#define OFF_WV  52428800LL
#define OFF_WO  69206016LL
#define OFF_WG  102760448LL
#define OFF_WU  203423744LL
#define OFF_WD  304087040LL

// ---------------- block reductions -----------------------------------------
__device__ __forceinline__ float blk_sum(float v) {
    __shared__ float s[8];
    #pragma unroll
    for (int o = 16; o; o >>= 1) v += __shfl_xor_sync(0xffffffffu, v, o);
    if ((threadIdx.x & 31) == 0) s[threadIdx.x >> 5] = v;
    __syncthreads();
    float t = 0.f;
    int nw = blockDim.x >> 5;
    #pragma unroll
    for (int i = 0; i < 8; i++) if (i < nw) t += s[i];
    __syncthreads();
    return t;
}
__device__ __forceinline__ float blk_max(float v) {
    __shared__ float s[8];
    #pragma unroll
    for (int o = 16; o; o >>= 1) v = fmaxf(v, __shfl_xor_sync(0xffffffffu, v, o));
    if ((threadIdx.x & 31) == 0) s[threadIdx.x >> 5] = v;
    __syncthreads();
    float t = -FLT_MAX;
    int nw = blockDim.x >> 5;
    #pragma unroll
    for (int i = 0; i < 8; i++) if (i < nw) t = fmaxf(t, s[i]);
    __syncthreads();
    return t;
}

// =================== bf16x3 tensor-core GEMM ================================
// C[M,N] = (ACCUM? C:0) + A @ B (+ bias), A=[M,K] row-major (hi/lo bf16),
// B=[K,N] row-major (hi/lo bf16). M,N mult of 128, K mult of 32.
#define GBM 128
#define GBN 128
#define GBK 32
// dynamic smem layout (bf16 elements):
// As: [2][2][128][40]  -> 20480 elems
// Bs: [2][2][32][136]  -> 17408 elems
#define AS_IDX(s,h,m,k) ((((s)*2+(h))*128 + (m))*40 + (k))
#define BS_IDX(s,h,kk,n) (20480 + (((s)*2+(h))*32 + (kk))*136 + (n))
#define GEMM_SMEM_BYTES ((20480 + 17408) * 2)

__device__ __forceinline__ void ldmx4(uint32_t* r, const __nv_bfloat16* p) {
    uint32_t a = (uint32_t)__cvta_generic_to_shared(p);
    asm volatile("ldmatrix.sync.aligned.m8n8.x4.shared.b16 {%0,%1,%2,%3}, [%4];"
        : "=r"(r[0]), "=r"(r[1]), "=r"(r[2]), "=r"(r[3]) : "r"(a));
}
__device__ __forceinline__ void ldmx4t(uint32_t* r, const __nv_bfloat16* p) {
    uint32_t a = (uint32_t)__cvta_generic_to_shared(p);
    asm volatile("ldmatrix.sync.aligned.m8n8.x4.trans.shared.b16 {%0,%1,%2,%3}, [%4];"
        : "=r"(r[0]), "=r"(r[1]), "=r"(r[2]), "=r"(r[3]) : "r"(a));
}
__device__ __forceinline__ void mma16816(float* c, const uint32_t* a, uint32_t b0, uint32_t b1) {
    asm volatile("mma.sync.aligned.m16n8k16.row.col.f32.bf16.bf16.f32 "
        "{%0,%1,%2,%3}, {%4,%5,%6,%7}, {%8,%9}, {%0,%1,%2,%3};"
        : "+f"(c[0]), "+f"(c[1]), "+f"(c[2]), "+f"(c[3])
        : "r"(a[0]), "r"(a[1]), "r"(a[2]), "r"(a[3]), "r"(b0), "r"(b1));
}
__device__ __forceinline__ void cp16(__nv_bfloat16* dst, const __nv_bfloat16* src) {
    uint32_t d = (uint32_t)__cvta_generic_to_shared(dst);
    asm volatile("cp.async.cg.shared.global [%0], [%1], 16;" :: "r"(d), "l"(src));
}

template<bool ACCUM, bool BIAS>
__global__ void __launch_bounds__(256) gemm_bf3(
    const __nv_bfloat16* __restrict__ Ah, const __nv_bfloat16* __restrict__ Al,
    const __nv_bfloat16* __restrict__ Bh, const __nv_bfloat16* __restrict__ Bl,
    const float* __restrict__ bias, float* __restrict__ C,
    int K, int lda, int ldb, int ldc)
{
    extern __shared__ __nv_bfloat16 sm[];
    const int bm = blockIdx.y * GBM;
    const int bn = blockIdx.x * GBN;
    const int tid = threadIdx.x;
    const int warp = tid >> 5, lane = tid & 31;
    const int wm = warp >> 2, wn = warp & 3;   // warps 2(M) x 4(N)

    // global load coords
    const int am = tid >> 2;          // 0..63
    const int ak = (tid & 3) * 8;     // 0,8,16,24
    const int bk = tid >> 4;          // 0..15
    const int bnn = (tid & 15) * 8;   // 0..120

    float acc[4][4][4];
    #pragma unroll
    for (int i = 0; i < 4; i++)
        #pragma unroll
        for (int j = 0; j < 4; j++)
            #pragma unroll
            for (int r = 0; r < 4; r++) acc[i][j][r] = 0.f;

    // ---- stage loader ----
    auto load_stage = [&](int s, int k0) {
        #pragma unroll
        for (int r = 0; r < 2; r++) {
            int m = am + r * 64;
            const __nv_bfloat16* gh = Ah + (long long)(bm + m) * lda + k0 + ak;
            const __nv_bfloat16* gl = Al + (long long)(bm + m) * lda + k0 + ak;
            cp16(&sm[AS_IDX(s, 0, m, ak)], gh);
            cp16(&sm[AS_IDX(s, 1, m, ak)], gl);
        }
        #pragma unroll
        for (int r = 0; r < 2; r++) {
            int kk = bk + r * 16;
            const __nv_bfloat16* gh = Bh + (long long)(k0 + kk) * ldb + bn + bnn;
            const __nv_bfloat16* gl = Bl + (long long)(k0 + kk) * ldb + bn + bnn;
            cp16(&sm[BS_IDX(s, 0, kk, bnn)], gh);
            cp16(&sm[BS_IDX(s, 1, kk, bnn)], gl);
        }
    };

    load_stage(0, 0);
    asm volatile("cp.async.commit_group;");

    int buf = 0;
    for (int k0 = 0; k0 < K; k0 += GBK) {
        if (k0 + GBK < K) load_stage(buf ^ 1, k0 + GBK);
        asm volatile("cp.async.commit_group;");
        asm volatile("cp.async.wait_group 1;");
        __syncthreads();

        #pragma unroll
        for (int kh = 0; kh < 2; kh++) {
            const int kk = kh * 16;
            uint32_t ah[4][4], al[4][4];
            #pragma unroll
            for (int mi = 0; mi < 4; mi++) {
                int r = wm * 64 + mi * 16 + (lane & 15);
                int c = kk + ((lane >> 4) << 3);
                ldmx4(ah[mi], &sm[AS_IDX(buf, 0, r, c)]);
                ldmx4(al[mi], &sm[AS_IDX(buf, 1, r, c)]);
            }
            uint32_t bh[2][4], bl[2][4];
            #pragma unroll
            for (int nj = 0; nj < 2; nj++) {
                int rb = kk + (lane & 15);
                int cb = wn * 32 + nj * 16 + ((lane >> 4) << 3);
                ldmx4t(bh[nj], &sm[BS_IDX(buf, 0, rb, cb)]);
                ldmx4t(bl[nj], &sm[BS_IDX(buf, 1, rb, cb)]);
            }
            #pragma unroll
            for (int mi = 0; mi < 4; mi++) {
                #pragma unroll
                for (int n8 = 0; n8 < 4; n8++) {
                    int nj = n8 >> 1, hf = n8 & 1;
                    uint32_t b0h = bh[nj][hf * 2], b1h = bh[nj][hf * 2 + 1];
                    uint32_t b0l = bl[nj][hf * 2], b1l = bl[nj][hf * 2 + 1];
                    mma16816(acc[mi][n8], ah[mi], b0h, b1h);
                    mma16816(acc[mi][n8], ah[mi], b0l, b1l);
                    mma16816(acc[mi][n8], al[mi], b0h, b1h);
                }
            }
        }
        __syncthreads();
        buf ^= 1;
    }

    // epilogue
    const int g = lane >> 2, tg = lane & 3;
    #pragma unroll
    for (int mi = 0; mi < 4; mi++) {
        #pragma unroll
        for (int n8 = 0; n8 < 4; n8++) {
            int row = bm + wm * 64 + mi * 16 + g;
            int col = bn + wn * 32 + n8 * 8 + tg * 2;
            float2 v0 = make_float2(acc[mi][n8][0], acc[mi][n8][1]);
            float2 v1 = make_float2(acc[mi][n8][2], acc[mi][n8][3]);
            if (BIAS) {
                v0.x += bias[col]; v0.y += bias[col + 1];
                v1.x += bias[col]; v1.y += bias[col + 1];
            }
            float2* p0 = (float2*)&C[(long long)row * ldc + col];
            float2* p1 = (float2*)&C[(long long)(row + 8) * ldc + col];
            if (ACCUM) {
                float2 c0 = *p0, c1 = *p1;
                v0.x += c0.x; v0.y += c0.y;
                v1.x += c1.x; v1.y += c1.y;
            }
            *p0 = v0; *p1 = v1;
        }
    }
}

// ---------------- fp32 SGEMM (attention only) -------------------------------
#define BM 128
#define BN 128
#define BKC 16
template<bool TRANSB>
__device__ __forceinline__ void gemm_dev(
    const float* __restrict__ A, const float* __restrict__ B,
    float* __restrict__ C, int K, int lda, int ldb, int ldc)
{
    __shared__ float As[BKC][BM + 4];
    __shared__ float Bs[BKC][BN + 4];
    const int bm = blockIdx.y * BM;
    const int bn = blockIdx.x * BN;
    const int tid = threadIdx.x;
    const int tx = tid & 15;
    const int ty = tid >> 4;
    const int a_m = tid >> 2;
    const int a_k = (tid & 3) * 4;

    float acc[8][8];
    #pragma unroll
    for (int i = 0; i < 8; i++)
        #pragma unroll
        for (int j = 0; j < 8; j++) acc[i][j] = 0.f;

    for (int k0 = 0; k0 < K; k0 += BKC) {
        #pragma unroll
        for (int r = 0; r < 2; r++) {
            int m = a_m + r * 64;
            float4 val = *(const float4*)(A + (long long)(bm + m) * lda + k0 + a_k);
            As[a_k + 0][m] = val.x; As[a_k + 1][m] = val.y;
            As[a_k + 2][m] = val.z; As[a_k + 3][m] = val.w;
        }
        if (!TRANSB) {
            int b_kr = tid >> 5;
            int b_n  = (tid & 31) * 4;
            #pragma unroll
            for (int r = 0; r < 2; r++) {
                int kk = b_kr + r * 8;
                float4 val = *(const float4*)(B + (long long)(k0 + kk) * ldb + bn + b_n);
                *(float4*)&Bs[kk][b_n] = val;
            }
        } else {
            #pragma unroll
            for (int r = 0; r < 2; r++) {
                int n = (tid >> 2) + r * 64;
                int kk = (tid & 3) * 4;
                float4 val = *(const float4*)(B + (long long)(bn + n) * ldb + k0 + kk);
                Bs[kk + 0][n] = val.x; Bs[kk + 1][n] = val.y;
                Bs[kk + 2][n] = val.z; Bs[kk + 3][n] = val.w;
            }
        }
        __syncthreads();
        #pragma unroll
        for (int kk = 0; kk < BKC; kk++) {
            float a[8], b[8];
            *(float4*)&a[0] = *(const float4*)&As[kk][ty * 8];
            *(float4*)&a[4] = *(const float4*)&As[kk][ty * 8 + 4];
            *(float4*)&b[0] = *(const float4*)&Bs[kk][tx * 8];
            *(float4*)&b[4] = *(const float4*)&Bs[kk][tx * 8 + 4];
            #pragma unroll
            for (int i = 0; i < 8; i++)
                #pragma unroll
                for (int j = 0; j < 8; j++)
                    acc[i][j] = fmaf(a[i], b[j], acc[i][j]);
        }
        __syncthreads();
    }
    #pragma unroll
    for (int i = 0; i < 8; i++) {
        long long m = bm + ty * 8 + i;
        #pragma unroll
        for (int j = 0; j < 8; j += 4) {
            int n = bn + tx * 8 + j;
            float4 r;
            r.x = acc[i][j]; r.y = acc[i][j+1]; r.z = acc[i][j+2]; r.w = acc[i][j+3];
            *(float4*)(C + m * ldc + n) = r;
        }
    }
}

__global__ void __launch_bounds__(256) qk_gemm() {
    int z = blockIdx.z;
    int b = z >> 4, h = z & 15, kvh = h >> 1;
    const float* A = g_q + ((long long)b * LL * NH + h) * HD;
    const float* B = g_k + ((long long)b * LL * NKV + kvh) * HD;
    float* C = g_s + (long long)z * LL * LL;
    gemm_dev<true>(A, B, C, HD, NH * HD, NKV * HD, LL);
}
__global__ void __launch_bounds__(256) av_gemm() {
    int z = blockIdx.z;
    int b = z >> 4, h = z & 15, kvh = h >> 1;
    const float* A = g_s + (long long)z * LL * LL;
    const float* B = g_v + ((long long)b * LL * NKV + kvh) * HD;
    float* C = g_o + ((long long)b * LL * NH + h) * HD;
    gemm_dev<false>(A, B, C, LL, LL, NKV * HD, NH * HD);
}

// ---------------- split helpers ---------------------------------------------
__global__ void split_k(const float* __restrict__ X,
                        __nv_bfloat16* __restrict__ hi, __nv_bfloat16* __restrict__ lo,
                        long long n) {
    long long i = (long long)blockIdx.x * blockDim.x + threadIdx.x;
    long long stride = (long long)gridDim.x * blockDim.x;
    for (; i < n; i += stride) {
        float v = X[i];
        __nv_bfloat16 h = __float2bfloat16(v);
        hi[i] = h;
        lo[i] = __float2bfloat16(v - __bfloat162float(h));
    }
}

// ---------------- RMSNorm -> f32 (final) ------------------------------------
__global__ void rmsnorm_k(const float* __restrict__ X, const float* __restrict__ w,
                          float* __restrict__ Y, int D) {
    long long row = blockIdx.x;
    const float* x = X + row * D;
    float* y = Y + row * D;
    float ss = 0.f;
    for (int j = threadIdx.x; j < D; j += blockDim.x) { float v = x[j]; ss += v * v; }
    float tot = blk_sum(ss);
    float r = rsqrtf(tot / (float)D + EPSF);
    for (int j = threadIdx.x; j < D; j += blockDim.x) y[j] = w[j] * x[j] * r;
}

// ---------------- RMSNorm -> bf16 hi/lo split -------------------------------
__global__ void rmsnorm_split_k(const float* __restrict__ X, const float* __restrict__ w,
                                __nv_bfloat16* __restrict__ hi, __nv_bfloat16* __restrict__ lo,
                                int D) {
    long long row = blockIdx.x;
    const float* x = X + row * D;
    float ss = 0.f;
    for (int j = threadIdx.x; j < D; j += blockDim.x) { float v = x[j]; ss += v * v; }
    float tot = blk_sum(ss);
    float r = rsqrtf(tot / (float)D + EPSF);
    for (int j = threadIdx.x; j < D; j += blockDim.x) {
        float v = w[j] * x[j] * r;
        __nv_bfloat16 h = __float2bfloat16(v);
        hi[row * D + j] = h;
        lo[row * D + j] = __float2bfloat16(v - __bfloat162float(h));
    }
}

// ---------------- RoPE table -------------------------------------------------
__global__ void rope_table_k() {
    int pos = blockIdx.x;
    int d = threadIdx.x;
    int j = d & 63;
    double inv = exp2(-(double)j * (19.931568569324174 / 64.0));
    double ang = (double)pos * inv;
    g_cos[pos * HD + d] = (float)cos(ang);
    g_sin[pos * HD + d] = (float)sin(ang);
}

// ---------------- per-head RMSNorm + RoPE -----------------------------------
__global__ void qknorm_rope_k(const float* __restrict__ wq, const float* __restrict__ wk) {
    int tok = blockIdx.x;
    int head = blockIdx.y;
    int d = threadIdx.x;
    float* base;
    const float* w;
    if (head < NH) { base = g_q + ((long long)tok * NH + head) * HD; w = wq; }
    else           { base = g_k + ((long long)tok * NKV + (head - NH)) * HD; w = wk; }

    float v = base[d];
    float ss = v * v;
    #pragma unroll
    for (int o = 16; o; o >>= 1) ss += __shfl_xor_sync(0xffffffffu, ss, o);
    __shared__ float wsum[4];
    __shared__ float smv[HD];
    if ((d & 31) == 0) wsum[d >> 5] = ss;
    __syncthreads();
    float tot = wsum[0] + wsum[1] + wsum[2] + wsum[3];
    float r = rsqrtf(tot / (float)HD + EPSF);
    float xn = w[d] * v * r;
    smv[d] = xn;
    __syncthreads();
    int pos = tok & (LL - 1);
    float c = g_cos[pos * HD + d];
    float s = g_sin[pos * HD + d];
    float rot = (d < 64) ? -smv[d + 64] : smv[d - 64];
    base[d] = xn * c + rot * s;
}

// ---------------- masked softmax --------------------------------------------
__global__ void softmax_k(const int* __restrict__ amask, int sliding) {
    long long row = blockIdx.x;
    int b = (int)(row / ((long long)NH * LL));
    int q = (int)(row & (LL - 1));
    float* p = g_s + row * LL;
    int tid = threadIdx.x;

    float vals[4];
    float mx = -FLT_MAX;
    #pragma unroll
    for (int t = 0; t < 4; t++) {
        int k = tid + t * 256;
        bool keep = (amask[b * LL + k] != 0);
        if (sliding) keep = keep && (abs(q - k) <= SW);
        float v = keep ? p[k] * ATT_SCALE : -FLT_MAX;
        vals[t] = v;
        mx = fmaxf(mx, v);
    }
    mx = blk_max(mx);
    float sum = 0.f;
    #pragma unroll
    for (int t = 0; t < 4; t++) { vals[t] = expf(vals[t] - mx); sum += vals[t]; }
    sum = blk_sum(sum);
    float inv = 1.0f / sum;
    #pragma unroll
    for (int t = 0; t < 4; t++) p[tid + t * 256] = vals[t] * inv;
}

// ---------------- SiLU(g)*u -> bf16 split -----------------------------------
__global__ void silu_mul_split_k(long long n) {
    long long i = (long long)blockIdx.x * blockDim.x + threadIdx.x;
    long long stride = (long long)gridDim.x * blockDim.x;
    for (; i < n; i += stride) {
        float x = g_g[i];
        float s = x / (1.0f + expf(-x));
        float v = s * g_u[i];
        __nv_bfloat16 h = __float2bfloat16(v);
        g_act_hi[i] = h;
        g_act_lo[i] = __float2bfloat16(v - __bfloat162float(h));
    }
}

// ---------------- host orchestration ----------------------------------------
extern "C" void kernel_launch(void* const* d_in, const int* in_sizes, int n_in,
                              void* d_out, int out_size) {
    (void)in_sizes; (void)n_in; (void)out_size;
    const float* x       = (const float*)d_in[0];
    const int*   amask   = (const int*)  d_in[1];
    const float* W_embed = (const float*)d_in[2];
    const float* b_embed = (const float*)d_in[3];
    const float* Wq      = (const float*)d_in[4];
    const float* Wk      = (const float*)d_in[5];
    const float* Wv      = (const float*)d_in[6];
    const float* Wo      = (const float*)d_in[7];
    const float* w_in    = (const float*)d_in[8];
    const float* w_post  = (const float*)d_in[9];
    const float* w_qn    = (const float*)d_in[10];
    const float* w_kn    = (const float*)d_in[11];
    const float* Wg      = (const float*)d_in[12];
    const float* Wu      = (const float*)d_in[13];
    const float* Wd      = (const float*)d_in[14];
    const float* w_final = (const float*)d_in[15];

    float *h, *gbuf, *ubuf, *ob;
    cudaGetSymbolAddress((void**)&h,    g_h);
    cudaGetSymbolAddress((void**)&gbuf, g_g);
    cudaGetSymbolAddress((void**)&ubuf, g_u);
    cudaGetSymbolAddress((void**)&ob,   g_o);
    float *qb, *kb, *vb;
    cudaGetSymbolAddress((void**)&qb, g_q);
    cudaGetSymbolAddress((void**)&kb, g_k);
    cudaGetSymbolAddress((void**)&vb, g_v);
    __nv_bfloat16 *whi, *wlo, *hnh, *hnl, *ach, *acl;
    cudaGetSymbolAddress((void**)&whi, g_whi);
    cudaGetSymbolAddress((void**)&wlo, g_wlo);
    cudaGetSymbolAddress((void**)&hnh, g_hn_hi);
    cudaGetSymbolAddress((void**)&hnl, g_hn_lo);
    cudaGetSymbolAddress((void**)&ach, g_act_hi);
    cudaGetSymbolAddress((void**)&acl, g_act_lo);

    // enable big dynamic smem on the gemm kernels
    cudaFuncSetAttribute(gemm_bf3<false,false>, cudaFuncAttributeMaxDynamicSharedMemorySize, GEMM_SMEM_BYTES);
    cudaFuncSetAttribute(gemm_bf3<true,false>,  cudaFuncAttributeMaxDynamicSharedMemorySize, GEMM_SMEM_BYTES);
    cudaFuncSetAttribute(gemm_bf3<false,true>,  cudaFuncAttributeMaxDynamicSharedMemorySize, GEMM_SMEM_BYTES);

    const int SPLIT_BLK = 256, SPLIT_GRID = 1184;
    // weight splits (hi/lo bf16)
    split_k<<<SPLIT_GRID, SPLIT_BLK>>>(W_embed, whi + OFF_EMB, wlo + OFF_EMB, (long long)TXT * HID);
    split_k<<<SPLIT_GRID, SPLIT_BLK>>>(Wq, whi + OFF_WQ, wlo + OFF_WQ, (long long)NLAYERS * HID * NH * HD);
    split_k<<<SPLIT_GRID, SPLIT_BLK>>>(Wk, whi + OFF_WK, wlo + OFF_WK, (long long)NLAYERS * HID * NKV * HD);
    split_k<<<SPLIT_GRID, SPLIT_BLK>>>(Wv, whi + OFF_WV, wlo + OFF_WV, (long long)NLAYERS * HID * NKV * HD);
    split_k<<<SPLIT_GRID, SPLIT_BLK>>>(Wo, whi + OFF_WO, wlo + OFF_WO, (long long)NLAYERS * NH * HD * HID);
    split_k<<<SPLIT_GRID, SPLIT_BLK>>>(Wg, whi + OFF_WG, wlo + OFF_WG, (long long)NLAYERS * HID * INTD);
    split_k<<<SPLIT_GRID, SPLIT_BLK>>>(Wu, whi + OFF_WU, wlo + OFF_WU, (long long)NLAYERS * HID * INTD);
    split_k<<<SPLIT_GRID, SPLIT_BLK>>>(Wd, whi + OFF_WD, wlo + OFF_WD, (long long)NLAYERS * INTD * HID);

    rope_table_k<<<LL, HD>>>();

    // embed: h = x @ W_embed + b  (bf16x3)
    split_k<<<SPLIT_GRID, SPLIT_BLK>>>(x, hnh, hnl, (long long)NTOK * TXT);
    gemm_bf3<false,true><<<dim3(HID / GBN, NTOK / GBM), 256, GEMM_SMEM_BYTES>>>(
        hnh, hnl, whi + OFF_EMB, wlo + OFF_EMB, b_embed, h, TXT, TXT, HID, HID);

    for (int i = 0; i < NLAYERS; i++) {
        rmsnorm_split_k<<<NTOK, 256>>>(h, w_in + (long long)i * HID, hnh, hnl, HID);

        gemm_bf3<false,false><<<dim3((NH*HD)/GBN, NTOK/GBM), 256, GEMM_SMEM_BYTES>>>(
            hnh, hnl, whi + OFF_WQ + (long long)i * HID * NH * HD,
            wlo + OFF_WQ + (long long)i * HID * NH * HD, nullptr, qb, HID, HID, NH*HD, NH*HD);
        gemm_bf3<false,false><<<dim3((NKV*HD)/GBN, NTOK/GBM), 256, GEMM_SMEM_BYTES>>>(
            hnh, hnl, whi + OFF_WK + (long long)i * HID * NKV * HD,
            wlo + OFF_WK + (long long)i * HID * NKV * HD, nullptr, kb, HID, HID, NKV*HD, NKV*HD);
        gemm_bf3<false,false><<<dim3((NKV*HD)/GBN, NTOK/GBM), 256, GEMM_SMEM_BYTES>>>(
            hnh, hnl, whi + OFF_WV + (long long)i * HID * NKV * HD,
            wlo + OFF_WV + (long long)i * HID * NKV * HD, nullptr, vb, HID, HID, NKV*HD, NKV*HD);

        qknorm_rope_k<<<dim3(NTOK, NH + NKV), HD>>>(
            w_qn + (long long)i * HD, w_kn + (long long)i * HD);

        qk_gemm<<<dim3(LL / BN, LL / BM, BB * NH), 256>>>();
        softmax_k<<<(long long)BB * NH * LL, 256>>>(amask, (i % 2 == 0) ? 1 : 0);
        av_gemm<<<dim3(HD / BN, LL / BM, BB * NH), 256>>>();

        // h += o @ Wo  (split o first)
        split_k<<<SPLIT_GRID, SPLIT_BLK>>>(ob, ach, acl, (long long)NTOK * NH * HD);
        gemm_bf3<true,false><<<dim3(HID/GBN, NTOK/GBM), 256, GEMM_SMEM_BYTES>>>(
            ach, acl, whi + OFF_WO + (long long)i * NH * HD * HID,
            wlo + OFF_WO + (long long)i * NH * HD * HID, nullptr, h, NH*HD, NH*HD, HID, HID);

        rmsnorm_split_k<<<NTOK, 256>>>(h, w_post + (long long)i * HID, hnh, hnl, HID);

        gemm_bf3<false,false><<<dim3(INTD/GBN, NTOK/GBM), 256, GEMM_SMEM_BYTES>>>(
            hnh, hnl, whi + OFF_WG + (long long)i * HID * INTD,
            wlo + OFF_WG + (long long)i * HID * INTD, nullptr, gbuf, HID, HID, INTD, INTD);
        gemm_bf3<false,false><<<dim3(INTD/GBN, NTOK/GBM), 256, GEMM_SMEM_BYTES>>>(
            hnh, hnl, whi + OFF_WU + (long long)i * HID * INTD,
            wlo + OFF_WU + (long long)i * HID * INTD, nullptr, ubuf, HID, HID, INTD, INTD);

        silu_mul_split_k<<<SPLIT_GRID, SPLIT_BLK>>>((long long)NTOK * INTD);

        gemm_bf3<true,false><<<dim3(HID/GBN, NTOK/GBM), 256, GEMM_SMEM_BYTES>>>(
            ach, acl, whi + OFF_WD + (long long)i * INTD * HID,
            wlo + OFF_WD + (long long)i * INTD * HID, nullptr, h, INTD, INTD, HID, HID);
    }

    rmsnorm_k<<<NTOK, 256>>>(h, w_final, (float*)d_out, HID);
}

// round 5
// speedup vs baseline: 2.5904x; 1.1398x over previous
#include <cuda_runtime.h>
#include <cuda_bf16.h>
#include <math.h>
#include <float.h>
#include <stdint.h>

// Problem constants
#define BB 2
#define LL 1024
#define TXT 1024
#define HID 2048
#define INTD 6144
#define NH 16
#define NKV 8
#define HD 128
#define NLAYERS 8
#define SW 128
#define EPSF 1e-6f
#define NTOK (BB*LL)          // 2048
#define ATT_SCALE 0.08838834764831845f  // 1/sqrt(128)

// ---------------- scratch (device globals; no allocation allowed) ----------
__device__ float g_h [NTOK*HID];
__device__ float g_q [NTOK*NH*HD];
__device__ float g_k [NTOK*NKV*HD];
__device__ float g_v [NTOK*NKV*HD];
__device__ float g_g [NTOK*INTD];
__device__ float g_u [NTOK*INTD];
__device__ float g_cos[LL*HD];
__device__ float g_sin[LL*HD];

// bf16 hi/lo splits
#define NWELEM 404750336LL
__device__ __nv_bfloat16 g_whi[NWELEM];
__device__ __nv_bfloat16 g_wlo[NWELEM];
__device__ __nv_bfloat16 g_hn_hi[NTOK*HID];
__device__ __nv_bfloat16 g_hn_lo[NTOK*HID];
__device__ __nv_bfloat16 g_act_hi[NTOK*INTD];
__device__ __nv_bfloat16 g_act_lo[NTOK*INTD];
__device__ __nv_bfloat16 g_qh[NTOK*NH*HD],  g_ql[NTOK*NH*HD];
__device__ __nv_bfloat16 g_kh[NTOK*NKV*HD], g_kl[NTOK*NKV*HD];
__device__ __nv_bfloat16 g_vh[NTOK*NKV*HD], g_vl[NTOK*NKV*HD];

// weight offsets inside g_whi/g_wlo
#define OFF_EMB 0LL
#define OFF_WQ  2097152LL
#define OFF_WK  35651584LL
#define OFF_WV  52428800LL
#define OFF_WO  69206016LL
#define OFF_WG  102760448LL
#define OFF_WU  203423744LL
#define OFF_WD  304087040LL

// ---------------- block reductions -----------------------------------------
__device__ __forceinline__ float blk_sum(float v) {
    __shared__ float s[8];
    #pragma unroll
    for (int o = 16; o; o >>= 1) v += __shfl_xor_sync(0xffffffffu, v, o);
    if ((threadIdx.x & 31) == 0) s[threadIdx.x >> 5] = v;
    __syncthreads();
    float t = 0.f;
    int nw = blockDim.x >> 5;
    #pragma unroll
    for (int i = 0; i < 8; i++) if (i < nw) t += s[i];
    __syncthreads();
    return t;
}

// ---------------- mma helpers -----------------------------------------------
__device__ __forceinline__ void ldmx4(uint32_t* r, const __nv_bfloat16* p) {
    uint32_t a = (uint32_t)__cvta_generic_to_shared(p);
    asm volatile("ldmatrix.sync.aligned.m8n8.x4.shared.b16 {%0,%1,%2,%3}, [%4];"
        : "=r"(r[0]), "=r"(r[1]), "=r"(r[2]), "=r"(r[3]) : "r"(a));
}
__device__ __forceinline__ void ldmx4t(uint32_t* r, const __nv_bfloat16* p) {
    uint32_t a = (uint32_t)__cvta_generic_to_shared(p);
    asm volatile("ldmatrix.sync.aligned.m8n8.x4.trans.shared.b16 {%0,%1,%2,%3}, [%4];"
        : "=r"(r[0]), "=r"(r[1]), "=r"(r[2]), "=r"(r[3]) : "r"(a));
}
__device__ __forceinline__ void mma16816(float* c, const uint32_t* a, uint32_t b0, uint32_t b1) {
    asm volatile("mma.sync.aligned.m16n8k16.row.col.f32.bf16.bf16.f32 "
        "{%0,%1,%2,%3}, {%4,%5,%6,%7}, {%8,%9}, {%0,%1,%2,%3};"
        : "+f"(c[0]), "+f"(c[1]), "+f"(c[2]), "+f"(c[3])
        : "r"(a[0]), "r"(a[1]), "r"(a[2]), "r"(a[3]), "r"(b0), "r"(b1));
}
__device__ __forceinline__ void cp16(__nv_bfloat16* dst, const __nv_bfloat16* src) {
    uint32_t d = (uint32_t)__cvta_generic_to_shared(dst);
    asm volatile("cp.async.cg.shared.global [%0], [%1], 16;" :: "r"(d), "l"(src));
}

// =================== bf16x3 tensor-core GEMM (linears) ======================
#define GBM 128
#define GBN 128
#define GBK 32
#define AS_IDX(s,h,m,k) ((((s)*2+(h))*128 + (m))*40 + (k))
#define BS_IDX(s,h,kk,n) (20480 + (((s)*2+(h))*32 + (kk))*136 + (n))
#define GEMM_SMEM_BYTES ((20480 + 17408) * 2)

template<bool ACCUM, bool BIAS>
__global__ void __launch_bounds__(256) gemm_bf3(
    const __nv_bfloat16* __restrict__ Ah, const __nv_bfloat16* __restrict__ Al,
    const __nv_bfloat16* __restrict__ Bh, const __nv_bfloat16* __restrict__ Bl,
    const float* __restrict__ bias, float* __restrict__ C,
    int K, int lda, int ldb, int ldc)
{
    extern __shared__ __nv_bfloat16 sm[];
    const int bm = blockIdx.y * GBM;
    const int bn = blockIdx.x * GBN;
    const int tid = threadIdx.x;
    const int warp = tid >> 5, lane = tid & 31;
    const int wm = warp >> 2, wn = warp & 3;

    const int am = tid >> 2;
    const int ak = (tid & 3) * 8;
    const int bk = tid >> 4;
    const int bnn = (tid & 15) * 8;

    float acc[4][4][4];
    #pragma unroll
    for (int i = 0; i < 4; i++)
        #pragma unroll
        for (int j = 0; j < 4; j++)
            #pragma unroll
            for (int r = 0; r < 4; r++) acc[i][j][r] = 0.f;

    auto load_stage = [&](int s, int k0) {
        #pragma unroll
        for (int r = 0; r < 2; r++) {
            int m = am + r * 64;
            cp16(&sm[AS_IDX(s, 0, m, ak)], Ah + (long long)(bm + m) * lda + k0 + ak);
            cp16(&sm[AS_IDX(s, 1, m, ak)], Al + (long long)(bm + m) * lda + k0 + ak);
        }
        #pragma unroll
        for (int r = 0; r < 2; r++) {
            int kk = bk + r * 16;
            cp16(&sm[BS_IDX(s, 0, kk, bnn)], Bh + (long long)(k0 + kk) * ldb + bn + bnn);
            cp16(&sm[BS_IDX(s, 1, kk, bnn)], Bl + (long long)(k0 + kk) * ldb + bn + bnn);
        }
    };

    load_stage(0, 0);
    asm volatile("cp.async.commit_group;");

    int buf = 0;
    for (int k0 = 0; k0 < K; k0 += GBK) {
        if (k0 + GBK < K) load_stage(buf ^ 1, k0 + GBK);
        asm volatile("cp.async.commit_group;");
        asm volatile("cp.async.wait_group 1;");
        __syncthreads();

        #pragma unroll
        for (int kh = 0; kh < 2; kh++) {
            const int kk = kh * 16;
            uint32_t ah[4][4], al[4][4];
            #pragma unroll
            for (int mi = 0; mi < 4; mi++) {
                int r = wm * 64 + mi * 16 + (lane & 15);
                int c = kk + ((lane >> 4) << 3);
                ldmx4(ah[mi], &sm[AS_IDX(buf, 0, r, c)]);
                ldmx4(al[mi], &sm[AS_IDX(buf, 1, r, c)]);
            }
            uint32_t bh[2][4], bl[2][4];
            #pragma unroll
            for (int nj = 0; nj < 2; nj++) {
                int rb = kk + (lane & 15);
                int cb = wn * 32 + nj * 16 + ((lane >> 4) << 3);
                ldmx4t(bh[nj], &sm[BS_IDX(buf, 0, rb, cb)]);
                ldmx4t(bl[nj], &sm[BS_IDX(buf, 1, rb, cb)]);
            }
            #pragma unroll
            for (int mi = 0; mi < 4; mi++) {
                #pragma unroll
                for (int n8 = 0; n8 < 4; n8++) {
                    int nj = n8 >> 1, hf = n8 & 1;
                    uint32_t b0h = bh[nj][hf * 2], b1h = bh[nj][hf * 2 + 1];
                    uint32_t b0l = bl[nj][hf * 2], b1l = bl[nj][hf * 2 + 1];
                    mma16816(acc[mi][n8], ah[mi], b0h, b1h);
                    mma16816(acc[mi][n8], ah[mi], b0l, b1l);
                    mma16816(acc[mi][n8], al[mi], b0h, b1h);
                }
            }
        }
        __syncthreads();
        buf ^= 1;
    }

    const int g = lane >> 2, tg = lane & 3;
    #pragma unroll
    for (int mi = 0; mi < 4; mi++) {
        #pragma unroll
        for (int n8 = 0; n8 < 4; n8++) {
            int row = bm + wm * 64 + mi * 16 + g;
            int col = bn + wn * 32 + n8 * 8 + tg * 2;
            float2 v0 = make_float2(acc[mi][n8][0], acc[mi][n8][1]);
            float2 v1 = make_float2(acc[mi][n8][2], acc[mi][n8][3]);
            if (BIAS) {
                v0.x += bias[col]; v0.y += bias[col + 1];
                v1.x += bias[col]; v1.y += bias[col + 1];
            }
            float2* p0 = (float2*)&C[(long long)row * ldc + col];
            float2* p1 = (float2*)&C[(long long)(row + 8) * ldc + col];
            if (ACCUM) {
                float2 c0 = *p0, c1 = *p1;
                v0.x += c0.x; v0.y += c0.y;
                v1.x += c1.x; v1.y += c1.y;
            }
            *p0 = v0; *p1 = v1;
        }
    }
}

// =================== fused flash attention ==================================
// grid (8 q-tiles, NH, BB); 256 threads = 8 warps; each warp owns 16 q rows.
// K-tiles of 64. bf16 hi/lo x3 for both QK^T and PV. Online softmax fp32.
#define FS_QS 136
#define FS_KS 136
#define FS_PS 72
#define SQH 0
#define SQL (SQH + 128*FS_QS)
#define SKH (SQL + 128*FS_QS)
#define SKL (SKH + 64*FS_KS)
#define SVH (SKL + 64*FS_KS)
#define SVL (SVH + 64*FS_KS)
#define SPH (SVL + 64*FS_KS)
#define SPL (SPH + 128*FS_PS)
#define FS_ELEMS (SPL + 128*FS_PS)
#define FLASH_SMEM_BYTES (FS_ELEMS*2 + 64*4)

__device__ __forceinline__ void split_pair(__nv_bfloat16* hi, __nv_bfloat16* lo,
                                           float a, float b) {
    __nv_bfloat16 ha = __float2bfloat16(a), hb = __float2bfloat16(b);
    __nv_bfloat162 hv; hv.x = ha; hv.y = hb;
    __nv_bfloat162 lv;
    lv.x = __float2bfloat16(a - __bfloat162float(ha));
    lv.y = __float2bfloat16(b - __bfloat162float(hb));
    *(__nv_bfloat162*)hi = hv;
    *(__nv_bfloat162*)lo = lv;
}

__global__ void __launch_bounds__(256) flash_attn_k(
    const __nv_bfloat16* __restrict__ Qh, const __nv_bfloat16* __restrict__ Ql,
    const __nv_bfloat16* __restrict__ Kh, const __nv_bfloat16* __restrict__ Kl,
    const __nv_bfloat16* __restrict__ Vh, const __nv_bfloat16* __restrict__ Vl,
    const int* __restrict__ amask,
    __nv_bfloat16* __restrict__ Ohi, __nv_bfloat16* __restrict__ Olo,
    int sliding)
{
    extern __shared__ __nv_bfloat16 fsm[];
    int* smask = (int*)&fsm[FS_ELEMS];
    const int qt = blockIdx.x, h = blockIdx.y, b = blockIdx.z;
    const int kvh = h >> 1;
    const int tid = threadIdx.x, warp = tid >> 5, lane = tid & 31;
    const int g = lane >> 2, tg = lane & 3;

    // ---- load Q tile (128x128 hi/lo) ----
    {
        int r = tid >> 1;
        int c0 = (tid & 1) * 64;
        long long gbase = ((long long)(b * LL + qt * 128 + r) * NH + h) * HD;
        #pragma unroll
        for (int i = 0; i < 8; i++) {
            int c = c0 + i * 8;
            cp16(&fsm[SQH + r * FS_QS + c], Qh + gbase + c);
            cp16(&fsm[SQL + r * FS_QS + c], Ql + gbase + c);
        }
    }
    asm volatile("cp.async.commit_group;");

    float m0 = -1e30f, m1 = -1e30f, l0 = 0.f, l1 = 0.f;
    float o_[16][4];
    #pragma unroll
    for (int n = 0; n < 16; n++)
        #pragma unroll
        for (int r = 0; r < 4; r++) o_[n][r] = 0.f;

    int kt0 = 0, kt1 = 16;
    if (sliding) { kt0 = max(0, 2 * qt - 2); kt1 = min(16, 2 * qt + 4); }

    for (int kt = kt0; kt < kt1; kt++) {
        // ---- load K/V tile (64x128 hi/lo each) + mask ----
        {
            int r = tid >> 2;
            int cb = (tid & 3) * 32;
            long long gb = ((long long)(b * LL + kt * 64 + r) * NKV + kvh) * HD;
            #pragma unroll
            for (int i = 0; i < 4; i++) {
                int c = cb + i * 8;
                cp16(&fsm[SKH + r * FS_KS + c], Kh + gb + c);
                cp16(&fsm[SKL + r * FS_KS + c], Kl + gb + c);
                cp16(&fsm[SVH + r * FS_KS + c], Vh + gb + c);
                cp16(&fsm[SVL + r * FS_KS + c], Vl + gb + c);
            }
        }
        if (tid < 64) smask[tid] = amask[b * LL + kt * 64 + tid];
        asm volatile("cp.async.commit_group;");
        asm volatile("cp.async.wait_group 0;");
        __syncthreads();

        // ---- S = Q K^T (bf16x3) ----
        // K tile in smem is [key][d] = B^T row-major => NON-trans ldmatrix,
        // rows indexed by key, cols by d; fragments: mat{0,2}=n0-7, mat{1,3}=n8-15.
        float s_[8][4];
        #pragma unroll
        for (int n = 0; n < 8; n++)
            #pragma unroll
            for (int r = 0; r < 4; r++) s_[n][r] = 0.f;

        #pragma unroll
        for (int kc = 0; kc < 8; kc++) {
            uint32_t ah[4], al[4];
            int qoff = (warp * 16 + (lane & 15)) * FS_QS + kc * 16 + ((lane >> 4) << 3);
            ldmx4(ah, &fsm[SQH + qoff]);
            ldmx4(al, &fsm[SQL + qoff]);
            #pragma unroll
            for (int np = 0; np < 4; np++) {
                uint32_t bh_[4], bl_[4];
                int koff = (np * 16 + (lane & 15)) * FS_KS + kc * 16 + ((lane >> 4) << 3);
                ldmx4(bh_, &fsm[SKH + koff]);
                ldmx4(bl_, &fsm[SKL + koff]);
                mma16816(s_[2*np],   ah, bh_[0], bh_[2]);
                mma16816(s_[2*np+1], ah, bh_[1], bh_[3]);
                mma16816(s_[2*np],   ah, bl_[0], bl_[2]);
                mma16816(s_[2*np+1], ah, bl_[1], bl_[3]);
                mma16816(s_[2*np],   al, bh_[0], bh_[2]);
                mma16816(s_[2*np+1], al, bh_[1], bh_[3]);
            }
        }

        // ---- mask + scale, online softmax ----
        int row0 = qt * 128 + warp * 16 + g;
        int row1 = row0 + 8;
        float tm0 = -1e30f, tm1 = -1e30f;
        #pragma unroll
        for (int n = 0; n < 8; n++) {
            int c0 = n * 8 + tg * 2;
            int gc0 = kt * 64 + c0, gc1 = gc0 + 1;
            bool am0 = smask[c0] != 0, am1 = smask[c0 + 1] != 0;
            bool b00 = am0 && (!sliding || abs(row0 - gc0) <= SW);
            bool b01 = am1 && (!sliding || abs(row0 - gc1) <= SW);
            bool b10 = am0 && (!sliding || abs(row1 - gc0) <= SW);
            bool b11 = am1 && (!sliding || abs(row1 - gc1) <= SW);
            s_[n][0] = b00 ? s_[n][0] * ATT_SCALE : -1e30f;
            s_[n][1] = b01 ? s_[n][1] * ATT_SCALE : -1e30f;
            s_[n][2] = b10 ? s_[n][2] * ATT_SCALE : -1e30f;
            s_[n][3] = b11 ? s_[n][3] * ATT_SCALE : -1e30f;
            tm0 = fmaxf(tm0, fmaxf(s_[n][0], s_[n][1]));
            tm1 = fmaxf(tm1, fmaxf(s_[n][2], s_[n][3]));
        }
        tm0 = fmaxf(tm0, __shfl_xor_sync(0xffffffffu, tm0, 1));
        tm0 = fmaxf(tm0, __shfl_xor_sync(0xffffffffu, tm0, 2));
        tm1 = fmaxf(tm1, __shfl_xor_sync(0xffffffffu, tm1, 1));
        tm1 = fmaxf(tm1, __shfl_xor_sync(0xffffffffu, tm1, 2));
        float nm0 = fmaxf(m0, tm0), nm1 = fmaxf(m1, tm1);
        float sf0 = expf(m0 - nm0), sf1 = expf(m1 - nm1);
        m0 = nm0; m1 = nm1;

        float ps0 = 0.f, ps1 = 0.f;
        int pr0 = (warp * 16 + g) * FS_PS;
        int pr1 = (warp * 16 + g + 8) * FS_PS;
        #pragma unroll
        for (int n = 0; n < 8; n++) {
            int c0 = n * 8 + tg * 2;
            float p00 = expf(s_[n][0] - m0), p01 = expf(s_[n][1] - m0);
            float p10 = expf(s_[n][2] - m1), p11 = expf(s_[n][3] - m1);
            ps0 += p00 + p01; ps1 += p10 + p11;
            split_pair(&fsm[SPH + pr0 + c0], &fsm[SPL + pr0 + c0], p00, p01);
            split_pair(&fsm[SPH + pr1 + c0], &fsm[SPL + pr1 + c0], p10, p11);
        }
        ps0 += __shfl_xor_sync(0xffffffffu, ps0, 1);
        ps0 += __shfl_xor_sync(0xffffffffu, ps0, 2);
        ps1 += __shfl_xor_sync(0xffffffffu, ps1, 1);
        ps1 += __shfl_xor_sync(0xffffffffu, ps1, 2);
        l0 = l0 * sf0 + ps0;
        l1 = l1 * sf1 + ps1;
        #pragma unroll
        for (int n = 0; n < 16; n++) {
            o_[n][0] *= sf0; o_[n][1] *= sf0;
            o_[n][2] *= sf1; o_[n][3] *= sf1;
        }
        __syncwarp();

        // ---- O += P V (bf16x3) ----
        // P [qrow][key] row-major = A; V [key][d] = [K][N] row-major => trans load.
        #pragma unroll
        for (int kc = 0; kc < 4; kc++) {
            uint32_t ph_[4], pl_[4];
            int poff = (warp * 16 + (lane & 15)) * FS_PS + kc * 16 + ((lane >> 4) << 3);
            ldmx4(ph_, &fsm[SPH + poff]);
            ldmx4(pl_, &fsm[SPL + poff]);
            #pragma unroll
            for (int np = 0; np < 8; np++) {
                uint32_t vh_[4], vl_[4];
                int voff = (kc * 16 + (lane & 15)) * FS_KS + np * 16 + ((lane >> 4) << 3);
                ldmx4t(vh_, &fsm[SVH + voff]);
                ldmx4t(vl_, &fsm[SVL + voff]);
                mma16816(o_[2*np],   ph_, vh_[0], vh_[1]);
                mma16816(o_[2*np+1], ph_, vh_[2], vh_[3]);
                mma16816(o_[2*np],   ph_, vl_[0], vl_[1]);
                mma16816(o_[2*np+1], ph_, vl_[2], vl_[3]);
                mma16816(o_[2*np],   pl_, vh_[0], vh_[1]);
                mma16816(o_[2*np+1], pl_, vh_[2], vh_[3]);
            }
        }
        __syncthreads();
    }

    // ---- epilogue: normalize, split, store ----
    float inv0 = 1.f / l0, inv1 = 1.f / l1;
    long long tok0 = (long long)b * LL + qt * 128 + warp * 16 + g;
    #pragma unroll
    for (int n = 0; n < 16; n++) {
        int col = h * HD + n * 8 + tg * 2;
        long long a0 = tok0 * (NH * HD) + col;
        long long a1 = (tok0 + 8) * (NH * HD) + col;
        split_pair(Ohi + a0, Olo + a0, o_[n][0] * inv0, o_[n][1] * inv0);
        split_pair(Ohi + a1, Olo + a1, o_[n][2] * inv1, o_[n][3] * inv1);
    }
}

// ---------------- split helper ----------------------------------------------
__global__ void split_k(const float* __restrict__ X,
                        __nv_bfloat16* __restrict__ hi, __nv_bfloat16* __restrict__ lo,
                        long long n) {
    long long i = (long long)blockIdx.x * blockDim.x + threadIdx.x;
    long long stride = (long long)gridDim.x * blockDim.x;
    for (; i < n; i += stride) {
        float v = X[i];
        __nv_bfloat16 h = __float2bfloat16(v);
        hi[i] = h;
        lo[i] = __float2bfloat16(v - __bfloat162float(h));
    }
}

// ---------------- RMSNorm variants ------------------------------------------
__global__ void rmsnorm_k(const float* __restrict__ X, const float* __restrict__ w,
                          float* __restrict__ Y, int D) {
    long long row = blockIdx.x;
    const float* x = X + row * D;
    float* y = Y + row * D;
    float ss = 0.f;
    for (int j = threadIdx.x; j < D; j += blockDim.x) { float v = x[j]; ss += v * v; }
    float tot = blk_sum(ss);
    float r = rsqrtf(tot / (float)D + EPSF);
    for (int j = threadIdx.x; j < D; j += blockDim.x) y[j] = w[j] * x[j] * r;
}

__global__ void rmsnorm_split_k(const float* __restrict__ X, const float* __restrict__ w,
                                __nv_bfloat16* __restrict__ hi, __nv_bfloat16* __restrict__ lo,
                                int D) {
    long long row = blockIdx.x;
    const float* x = X + row * D;
    float ss = 0.f;
    for (int j = threadIdx.x; j < D; j += blockDim.x) { float v = x[j]; ss += v * v; }
    float tot = blk_sum(ss);
    float r = rsqrtf(tot / (float)D + EPSF);
    for (int j = threadIdx.x; j < D; j += blockDim.x) {
        float v = w[j] * x[j] * r;
        __nv_bfloat16 h = __float2bfloat16(v);
        hi[row * D + j] = h;
        lo[row * D + j] = __float2bfloat16(v - __bfloat162float(h));
    }
}

// ---------------- RoPE table -------------------------------------------------
__global__ void rope_table_k() {
    int pos = blockIdx.x;
    int d = threadIdx.x;
    int j = d & 63;
    double inv = exp2(-(double)j * (19.931568569324174 / 64.0));
    double ang = (double)pos * inv;
    g_cos[pos * HD + d] = (float)cos(ang);
    g_sin[pos * HD + d] = (float)sin(ang);
}

// ---------------- per-head RMSNorm + RoPE -> bf16 hi/lo ---------------------
__global__ void qknorm_rope_k(const float* __restrict__ wq, const float* __restrict__ wk) {
    int tok = blockIdx.x;
    int head = blockIdx.y;
    int d = threadIdx.x;
    const float* base;
    const float* w;
    long long idx;
    if (head < NH) {
        idx = ((long long)tok * NH + head) * HD + d;
        base = g_q + ((long long)tok * NH + head) * HD;
        w = wq;
    } else {
        idx = ((long long)tok * NKV + (head - NH)) * HD + d;
        base = g_k + ((long long)tok * NKV + (head - NH)) * HD;
        w = wk;
    }

    float v = base[d];
    float ss = v * v;
    #pragma unroll
    for (int o = 16; o; o >>= 1) ss += __shfl_xor_sync(0xffffffffu, ss, o);
    __shared__ float wsum[4];
    __shared__ float smv[HD];
    if ((d & 31) == 0) wsum[d >> 5] = ss;
    __syncthreads();
    float tot = wsum[0] + wsum[1] + wsum[2] + wsum[3];
    float r = rsqrtf(tot / (float)HD + EPSF);
    float xn = w[d] * v * r;
    smv[d] = xn;
    __syncthreads();
    int pos = tok & (LL - 1);
    float c = g_cos[pos * HD + d];
    float s = g_sin[pos * HD + d];
    float rot = (d < 64) ? -smv[d + 64] : smv[d - 64];
    float fin = xn * c + rot * s;
    __nv_bfloat16 hi = __float2bfloat16(fin);
    __nv_bfloat16 lo = __float2bfloat16(fin - __bfloat162float(hi));
    if (head < NH) { g_qh[idx] = hi; g_ql[idx] = lo; }
    else           { g_kh[idx] = hi; g_kl[idx] = lo; }
}

// ---------------- SiLU(g)*u -> bf16 split -----------------------------------
__global__ void silu_mul_split_k(long long n) {
    long long i = (long long)blockIdx.x * blockDim.x + threadIdx.x;
    long long stride = (long long)gridDim.x * blockDim.x;
    for (; i < n; i += stride) {
        float x = g_g[i];
        float s = x / (1.0f + expf(-x));
        float v = s * g_u[i];
        __nv_bfloat16 h = __float2bfloat16(v);
        g_act_hi[i] = h;
        g_act_lo[i] = __float2bfloat16(v - __bfloat162float(h));
    }
}

// ---------------- host orchestration ----------------------------------------
extern "C" void kernel_launch(void* const* d_in, const int* in_sizes, int n_in,
                              void* d_out, int out_size) {
    (void)in_sizes; (void)n_in; (void)out_size;
    const float* x       = (const float*)d_in[0];
    const int*   amask   = (const int*)  d_in[1];
    const float* W_embed = (const float*)d_in[2];
    const float* b_embed = (const float*)d_in[3];
    const float* Wq      = (const float*)d_in[4];
    const float* Wk      = (const float*)d_in[5];
    const float* Wv      = (const float*)d_in[6];
    const float* Wo      = (const float*)d_in[7];
    const float* w_in    = (const float*)d_in[8];
    const float* w_post  = (const float*)d_in[9];
    const float* w_qn    = (const float*)d_in[10];
    const float* w_kn    = (const float*)d_in[11];
    const float* Wg      = (const float*)d_in[12];
    const float* Wu      = (const float*)d_in[13];
    const float* Wd      = (const float*)d_in[14];
    const float* w_final = (const float*)d_in[15];

    float *h, *gbuf, *ubuf;
    cudaGetSymbolAddress((void**)&h,    g_h);
    cudaGetSymbolAddress((void**)&gbuf, g_g);
    cudaGetSymbolAddress((void**)&ubuf, g_u);
    float *qb, *kb, *vb;
    cudaGetSymbolAddress((void**)&qb, g_q);
    cudaGetSymbolAddress((void**)&kb, g_k);
    cudaGetSymbolAddress((void**)&vb, g_v);
    __nv_bfloat16 *whi, *wlo, *hnh, *hnl, *ach, *acl;
    cudaGetSymbolAddress((void**)&whi, g_whi);
    cudaGetSymbolAddress((void**)&wlo, g_wlo);
    cudaGetSymbolAddress((void**)&hnh, g_hn_hi);
    cudaGetSymbolAddress((void**)&hnl, g_hn_lo);
    cudaGetSymbolAddress((void**)&ach, g_act_hi);
    cudaGetSymbolAddress((void**)&acl, g_act_lo);
    __nv_bfloat16 *qh, *ql, *kh, *kl, *vh, *vl;
    cudaGetSymbolAddress((void**)&qh, g_qh);
    cudaGetSymbolAddress((void**)&ql, g_ql);
    cudaGetSymbolAddress((void**)&kh, g_kh);
    cudaGetSymbolAddress((void**)&kl, g_kl);
    cudaGetSymbolAddress((void**)&vh, g_vh);
    cudaGetSymbolAddress((void**)&vl, g_vl);

    cudaFuncSetAttribute(gemm_bf3<false,false>, cudaFuncAttributeMaxDynamicSharedMemorySize, GEMM_SMEM_BYTES);
    cudaFuncSetAttribute(gemm_bf3<true,false>,  cudaFuncAttributeMaxDynamicSharedMemorySize, GEMM_SMEM_BYTES);
    cudaFuncSetAttribute(gemm_bf3<false,true>,  cudaFuncAttributeMaxDynamicSharedMemorySize, GEMM_SMEM_BYTES);
    cudaFuncSetAttribute(flash_attn_k, cudaFuncAttributeMaxDynamicSharedMemorySize, FLASH_SMEM_BYTES);

    const int SPLIT_BLK = 256, SPLIT_GRID = 1184;
    split_k<<<SPLIT_GRID, SPLIT_BLK>>>(W_embed, whi + OFF_EMB, wlo + OFF_EMB, (long long)TXT * HID);
    split_k<<<SPLIT_GRID, SPLIT_BLK>>>(Wq, whi + OFF_WQ, wlo + OFF_WQ, (long long)NLAYERS * HID * NH * HD);
    split_k<<<SPLIT_GRID, SPLIT_BLK>>>(Wk, whi + OFF_WK, wlo + OFF_WK, (long long)NLAYERS * HID * NKV * HD);
    split_k<<<SPLIT_GRID, SPLIT_BLK>>>(Wv, whi + OFF_WV, wlo + OFF_WV, (long long)NLAYERS * HID * NKV * HD);
    split_k<<<SPLIT_GRID, SPLIT_BLK>>>(Wo, whi + OFF_WO, wlo + OFF_WO, (long long)NLAYERS * NH * HD * HID);
    split_k<<<SPLIT_GRID, SPLIT_BLK>>>(Wg, whi + OFF_WG, wlo + OFF_WG, (long long)NLAYERS * HID * INTD);
    split_k<<<SPLIT_GRID, SPLIT_BLK>>>(Wu, whi + OFF_WU, wlo + OFF_WU, (long long)NLAYERS * HID * INTD);
    split_k<<<SPLIT_GRID, SPLIT_BLK>>>(Wd, whi + OFF_WD, wlo + OFF_WD, (long long)NLAYERS * INTD * HID);

    rope_table_k<<<LL, HD>>>();

    split_k<<<SPLIT_GRID, SPLIT_BLK>>>(x, hnh, hnl, (long long)NTOK * TXT);
    gemm_bf3<false,true><<<dim3(HID / GBN, NTOK / GBM), 256, GEMM_SMEM_BYTES>>>(
        hnh, hnl, whi + OFF_EMB, wlo + OFF_EMB, b_embed, h, TXT, TXT, HID, HID);

    for (int i = 0; i < NLAYERS; i++) {
        rmsnorm_split_k<<<NTOK, 256>>>(h, w_in + (long long)i * HID, hnh, hnl, HID);

        gemm_bf3<false,false><<<dim3((NH*HD)/GBN, NTOK/GBM), 256, GEMM_SMEM_BYTES>>>(
            hnh, hnl, whi + OFF_WQ + (long long)i * HID * NH * HD,
            wlo + OFF_WQ + (long long)i * HID * NH * HD, nullptr, qb, HID, HID, NH*HD, NH*HD);
        gemm_bf3<false,false><<<dim3((NKV*HD)/GBN, NTOK/GBM), 256, GEMM_SMEM_BYTES>>>(
            hnh, hnl, whi + OFF_WK + (long long)i * HID * NKV * HD,
            wlo + OFF_WK + (long long)i * HID * NKV * HD, nullptr, kb, HID, HID, NKV*HD, NKV*HD);
        gemm_bf3<false,false><<<dim3((NKV*HD)/GBN, NTOK/GBM), 256, GEMM_SMEM_BYTES>>>(
            hnh, hnl, whi + OFF_WV + (long long)i * HID * NKV * HD,
            wlo + OFF_WV + (long long)i * HID * NKV * HD, nullptr, vb, HID, HID, NKV*HD, NKV*HD);

        qknorm_rope_k<<<dim3(NTOK, NH + NKV), HD>>>(
            w_qn + (long long)i * HD, w_kn + (long long)i * HD);
        split_k<<<SPLIT_GRID, SPLIT_BLK>>>(vb, vh, vl, (long long)NTOK * NKV * HD);

        flash_attn_k<<<dim3(8, NH, BB), 256, FLASH_SMEM_BYTES>>>(
            qh, ql, kh, kl, vh, vl, amask, ach, acl, (i % 2 == 0) ? 1 : 0);

        gemm_bf3<true,false><<<dim3(HID/GBN, NTOK/GBM), 256, GEMM_SMEM_BYTES>>>(
            ach, acl, whi + OFF_WO + (long long)i * NH * HD * HID,
            wlo + OFF_WO + (long long)i * NH * HD * HID, nullptr, h, NH*HD, NH*HD, HID, HID);

        rmsnorm_split_k<<<NTOK, 256>>>(h, w_post + (long long)i * HID, hnh, hnl, HID);

        gemm_bf3<false,false><<<dim3(INTD/GBN, NTOK/GBM), 256, GEMM_SMEM_BYTES>>>(
            hnh, hnl, whi + OFF_WG + (long long)i * HID * INTD,
            wlo + OFF_WG + (long long)i * HID * INTD, nullptr, gbuf, HID, HID, INTD, INTD);
        gemm_bf3<false,false><<<dim3(INTD/GBN, NTOK/GBM), 256, GEMM_SMEM_BYTES>>>(
            hnh, hnl, whi + OFF_WU + (long long)i * HID * INTD,
            wlo + OFF_WU + (long long)i * HID * INTD, nullptr, ubuf, HID, HID, INTD, INTD);

        silu_mul_split_k<<<SPLIT_GRID, SPLIT_BLK>>>((long long)NTOK * INTD);

        gemm_bf3<true,false><<<dim3(HID/GBN, NTOK/GBM), 256, GEMM_SMEM_BYTES>>>(
            ach, acl, whi + OFF_WD + (long long)i * INTD * HID,
            wlo + OFF_WD + (long long)i * INTD * HID, nullptr, h, INTD, INTD, HID, HID);
    }

    rmsnorm_k<<<NTOK, 256>>>(h, w_final, (float*)d_out, HID);
}

// round 8
// speedup vs baseline: 2.6744x; 1.0324x over previous
#include <cuda_runtime.h>
#include <cuda_bf16.h>
#include <math.h>
#include <float.h>
#include <stdint.h>

// Problem constants
#define BB 2
#define LL 1024
#define TXT 1024
#define HID 2048
#define INTD 6144
#define NH 16
#define NKV 8
#define HD 128
#define NLAYERS 8
#define SW 128
#define EPSF 1e-6f
#define NTOK (BB*LL)
#define ATT_SCALE 0.08838834764831845f

// ---------------- scratch (device globals; no allocation allowed) ----------
__device__ float g_h  [NTOK*HID];
__device__ float g_qkv[NTOK*4096];          // q|k|v fused per token
__device__ float g_gu [NTOK*2*INTD];        // gate|up fused per token
__device__ float g_cos[LL*HD];
__device__ float g_sin[LL*HD];

// bf16 hi/lo splits; fused-column weight layout
#define NWELEM 404750336LL
__device__ __nv_bfloat16 g_whi[NWELEM];
__device__ __nv_bfloat16 g_wlo[NWELEM];
__device__ __nv_bfloat16 g_hn_hi[NTOK*HID];
__device__ __nv_bfloat16 g_hn_lo[NTOK*HID];
__device__ __nv_bfloat16 g_act_hi[NTOK*INTD];
__device__ __nv_bfloat16 g_act_lo[NTOK*INTD];
__device__ __nv_bfloat16 g_qh[NTOK*NH*HD],  g_ql[NTOK*NH*HD];
__device__ __nv_bfloat16 g_kh[NTOK*NKV*HD], g_kl[NTOK*NKV*HD];
__device__ __nv_bfloat16 g_vh[NTOK*NKV*HD], g_vl[NTOK*NKV*HD];

// offsets (bf16 elements) inside g_whi/g_wlo
#define OFF_EMB 0LL                 // [1024 x 2048]
#define OFF_QKV 2097152LL           // 8 x [2048 x 4096]  (q|k|v cols)
#define OFF_WO  69206016LL          // 8 x [2048 x 2048]
#define OFF_GU  102760448LL         // 8 x [2048 x 12288] (g|u cols)
#define OFF_WD  304087040LL         // 8 x [6144 x 2048]

// ---------------- block reductions -----------------------------------------
__device__ __forceinline__ float blk_sum(float v) {
    __shared__ float s[8];
    #pragma unroll
    for (int o = 16; o; o >>= 1) v += __shfl_xor_sync(0xffffffffu, v, o);
    if ((threadIdx.x & 31) == 0) s[threadIdx.x >> 5] = v;
    __syncthreads();
    float t = 0.f;
    int nw = blockDim.x >> 5;
    #pragma unroll
    for (int i = 0; i < 8; i++) if (i < nw) t += s[i];
    __syncthreads();
    return t;
}

// ---------------- mma helpers -----------------------------------------------
__device__ __forceinline__ void ldmx4(uint32_t* r, const __nv_bfloat16* p) {
    uint32_t a = (uint32_t)__cvta_generic_to_shared(p);
    asm volatile("ldmatrix.sync.aligned.m8n8.x4.shared.b16 {%0,%1,%2,%3}, [%4];"
        : "=r"(r[0]), "=r"(r[1]), "=r"(r[2]), "=r"(r[3]) : "r"(a));
}
__device__ __forceinline__ void ldmx4t(uint32_t* r, const __nv_bfloat16* p) {
    uint32_t a = (uint32_t)__cvta_generic_to_shared(p);
    asm volatile("ldmatrix.sync.aligned.m8n8.x4.trans.shared.b16 {%0,%1,%2,%3}, [%4];"
        : "=r"(r[0]), "=r"(r[1]), "=r"(r[2]), "=r"(r[3]) : "r"(a));
}
__device__ __forceinline__ void mma16816(float* c, const uint32_t* a, uint32_t b0, uint32_t b1) {
    asm volatile("mma.sync.aligned.m16n8k16.row.col.f32.bf16.bf16.f32 "
        "{%0,%1,%2,%3}, {%4,%5,%6,%7}, {%8,%9}, {%0,%1,%2,%3};"
        : "+f"(c[0]), "+f"(c[1]), "+f"(c[2]), "+f"(c[3])
        : "r"(a[0]), "r"(a[1]), "r"(a[2]), "r"(a[3]), "r"(b0), "r"(b1));
}
__device__ __forceinline__ void cp16(void* dst, const void* src) {
    uint32_t d = (uint32_t)__cvta_generic_to_shared(dst);
    asm volatile("cp.async.cg.shared.global [%0], [%1], 16;" :: "r"(d), "l"(src));
}

// =================== bf16x3 tensor-core GEMM (linears) ======================
#define GBM 128
#define GBN 128
#define GBK 32
#define AS_IDX(s,h,m,k) ((((s)*2+(h))*128 + (m))*40 + (k))
#define BS_IDX(s,h,kk,n) (20480 + (((s)*2+(h))*32 + (kk))*136 + (n))
#define GEMM_SMEM_BYTES ((20480 + 17408) * 2)

template<bool ACCUM, bool BIAS>
__global__ void __launch_bounds__(256, 2) gemm_bf3(
    const __nv_bfloat16* __restrict__ Ah, const __nv_bfloat16* __restrict__ Al,
    const __nv_bfloat16* __restrict__ Bh, const __nv_bfloat16* __restrict__ Bl,
    const float* __restrict__ bias, float* __restrict__ C,
    int K, int lda, int ldb, int ldc)
{
    extern __shared__ __nv_bfloat16 sm[];
    const int bm = blockIdx.y * GBM;
    const int bn = blockIdx.x * GBN;
    const int tid = threadIdx.x;
    const int warp = tid >> 5, lane = tid & 31;
    const int wm = warp >> 2, wn = warp & 3;

    const int am = tid >> 2;
    const int ak = (tid & 3) * 8;
    const int bk = tid >> 4;
    const int bnn = (tid & 15) * 8;

    float acc[4][4][4];
    #pragma unroll
    for (int i = 0; i < 4; i++)
        #pragma unroll
        for (int j = 0; j < 4; j++)
            #pragma unroll
            for (int r = 0; r < 4; r++) acc[i][j][r] = 0.f;

    auto load_stage = [&](int s, int k0) {
        #pragma unroll
        for (int r = 0; r < 2; r++) {
            int m = am + r * 64;
            cp16(&sm[AS_IDX(s, 0, m, ak)], Ah + (long long)(bm + m) * lda + k0 + ak);
            cp16(&sm[AS_IDX(s, 1, m, ak)], Al + (long long)(bm + m) * lda + k0 + ak);
        }
        #pragma unroll
        for (int r = 0; r < 2; r++) {
            int kk = bk + r * 16;
            cp16(&sm[BS_IDX(s, 0, kk, bnn)], Bh + (long long)(k0 + kk) * ldb + bn + bnn);
            cp16(&sm[BS_IDX(s, 1, kk, bnn)], Bl + (long long)(k0 + kk) * ldb + bn + bnn);
        }
    };

    load_stage(0, 0);
    asm volatile("cp.async.commit_group;");

    int buf = 0;
    for (int k0 = 0; k0 < K; k0 += GBK) {
        if (k0 + GBK < K) load_stage(buf ^ 1, k0 + GBK);
        asm volatile("cp.async.commit_group;");
        asm volatile("cp.async.wait_group 1;");
        __syncthreads();

        #pragma unroll
        for (int kh = 0; kh < 2; kh++) {
            const int kk = kh * 16;
            uint32_t ah[4][4], al[4][4];
            #pragma unroll
            for (int mi = 0; mi < 4; mi++) {
                int r = wm * 64 + mi * 16 + (lane & 15);
                int c = kk + ((lane >> 4) << 3);
                ldmx4(ah[mi], &sm[AS_IDX(buf, 0, r, c)]);
                ldmx4(al[mi], &sm[AS_IDX(buf, 1, r, c)]);
            }
            uint32_t bh[2][4], bl[2][4];
            #pragma unroll
            for (int nj = 0; nj < 2; nj++) {
                int rb = kk + (lane & 15);
                int cb = wn * 32 + nj * 16 + ((lane >> 4) << 3);
                ldmx4t(bh[nj], &sm[BS_IDX(buf, 0, rb, cb)]);
                ldmx4t(bl[nj], &sm[BS_IDX(buf, 1, rb, cb)]);
            }
            #pragma unroll
            for (int mi = 0; mi < 4; mi++) {
                #pragma unroll
                for (int n8 = 0; n8 < 4; n8++) {
                    int nj = n8 >> 1, hf = n8 & 1;
                    uint32_t b0h = bh[nj][hf * 2], b1h = bh[nj][hf * 2 + 1];
                    uint32_t b0l = bl[nj][hf * 2], b1l = bl[nj][hf * 2 + 1];
                    mma16816(acc[mi][n8], ah[mi], b0h, b1h);
                    mma16816(acc[mi][n8], ah[mi], b0l, b1l);
                    mma16816(acc[mi][n8], al[mi], b0h, b1h);
                }
            }
        }
        __syncthreads();
        buf ^= 1;
    }

    const int g = lane >> 2, tg = lane & 3;
    #pragma unroll
    for (int mi = 0; mi < 4; mi++) {
        #pragma unroll
        for (int n8 = 0; n8 < 4; n8++) {
            int row = bm + wm * 64 + mi * 16 + g;
            int col = bn + wn * 32 + n8 * 8 + tg * 2;
            float2 v0 = make_float2(acc[mi][n8][0], acc[mi][n8][1]);
            float2 v1 = make_float2(acc[mi][n8][2], acc[mi][n8][3]);
            if (BIAS) {
                v0.x += bias[col]; v0.y += bias[col + 1];
                v1.x += bias[col]; v1.y += bias[col + 1];
            }
            float2* p0 = (float2*)&C[(long long)row * ldc + col];
            float2* p1 = (float2*)&C[(long long)(row + 8) * ldc + col];
            if (ACCUM) {
                float2 c0 = *p0, c1 = *p1;
                v0.x += c0.x; v0.y += c0.y;
                v1.x += c1.x; v1.y += c1.y;
            }
            *p0 = v0; *p1 = v1;
        }
    }
}

// =================== fused flash attention (R5, proven) =====================
#define FS_QS 136
#define FS_KS 136
#define FS_PS 72
#define SQH 0
#define SQL (SQH + 128*FS_QS)
#define SKH (SQL + 128*FS_QS)
#define SKL (SKH + 64*FS_KS)
#define SVH (SKL + 64*FS_KS)
#define SVL (SVH + 64*FS_KS)
#define SPH (SVL + 64*FS_KS)
#define SPL (SPH + 128*FS_PS)
#define FS_ELEMS (SPL + 128*FS_PS)
#define FLASH_SMEM_BYTES (FS_ELEMS*2 + 64*4)

__device__ __forceinline__ void split_pair(__nv_bfloat16* hi, __nv_bfloat16* lo,
                                           float a, float b) {
    __nv_bfloat16 ha = __float2bfloat16(a), hb = __float2bfloat16(b);
    __nv_bfloat162 hv; hv.x = ha; hv.y = hb;
    __nv_bfloat162 lv;
    lv.x = __float2bfloat16(a - __bfloat162float(ha));
    lv.y = __float2bfloat16(b - __bfloat162float(hb));
    *(__nv_bfloat162*)hi = hv;
    *(__nv_bfloat162*)lo = lv;
}

__global__ void __launch_bounds__(256) flash_attn_k(
    const __nv_bfloat16* __restrict__ Qh, const __nv_bfloat16* __restrict__ Ql,
    const __nv_bfloat16* __restrict__ Kh, const __nv_bfloat16* __restrict__ Kl,
    const __nv_bfloat16* __restrict__ Vh, const __nv_bfloat16* __restrict__ Vl,
    const int* __restrict__ amask,
    __nv_bfloat16* __restrict__ Ohi, __nv_bfloat16* __restrict__ Olo,
    int sliding)
{
    extern __shared__ __nv_bfloat16 fsm[];
    int* smask = (int*)&fsm[FS_ELEMS];
    const int qt = blockIdx.x, h = blockIdx.y, b = blockIdx.z;
    const int kvh = h >> 1;
    const int tid = threadIdx.x, warp = tid >> 5, lane = tid & 31;
    const int g = lane >> 2, tg = lane & 3;

    {
        int r = tid >> 1;
        int c0 = (tid & 1) * 64;
        long long gbase = ((long long)(b * LL + qt * 128 + r) * NH + h) * HD;
        #pragma unroll
        for (int i = 0; i < 8; i++) {
            int c = c0 + i * 8;
            cp16(&fsm[SQH + r * FS_QS + c], Qh + gbase + c);
            cp16(&fsm[SQL + r * FS_QS + c], Ql + gbase + c);
        }
    }
    asm volatile("cp.async.commit_group;");

    float m0 = -1e30f, m1 = -1e30f, l0 = 0.f, l1 = 0.f;
    float o_[16][4];
    #pragma unroll
    for (int n = 0; n < 16; n++)
        #pragma unroll
        for (int r = 0; r < 4; r++) o_[n][r] = 0.f;

    int kt0 = 0, kt1 = 16;
    if (sliding) { kt0 = max(0, 2 * qt - 2); kt1 = min(16, 2 * qt + 4); }

    for (int kt = kt0; kt < kt1; kt++) {
        {
            int r = tid >> 2;
            int cb = (tid & 3) * 32;
            long long gb = ((long long)(b * LL + kt * 64 + r) * NKV + kvh) * HD;
            #pragma unroll
            for (int i = 0; i < 4; i++) {
                int c = cb + i * 8;
                cp16(&fsm[SKH + r * FS_KS + c], Kh + gb + c);
                cp16(&fsm[SKL + r * FS_KS + c], Kl + gb + c);
                cp16(&fsm[SVH + r * FS_KS + c], Vh + gb + c);
                cp16(&fsm[SVL + r * FS_KS + c], Vl + gb + c);
            }
        }
        if (tid < 64) smask[tid] = amask[b * LL + kt * 64 + tid];
        asm volatile("cp.async.commit_group;");
        asm volatile("cp.async.wait_group 0;");
        __syncthreads();

        float s_[8][4];
        #pragma unroll
        for (int n = 0; n < 8; n++)
            #pragma unroll
            for (int r = 0; r < 4; r++) s_[n][r] = 0.f;

        #pragma unroll
        for (int kc = 0; kc < 8; kc++) {
            uint32_t ah[4], al[4];
            int qoff = (warp * 16 + (lane & 15)) * FS_QS + kc * 16 + ((lane >> 4) << 3);
            ldmx4(ah, &fsm[SQH + qoff]);
            ldmx4(al, &fsm[SQL + qoff]);
            #pragma unroll
            for (int np = 0; np < 4; np++) {
                uint32_t bh_[4], bl_[4];
                int koff = (np * 16 + (lane & 15)) * FS_KS + kc * 16 + ((lane >> 4) << 3);
                ldmx4(bh_, &fsm[SKH + koff]);
                ldmx4(bl_, &fsm[SKL + koff]);
                mma16816(s_[2*np],   ah, bh_[0], bh_[2]);
                mma16816(s_[2*np+1], ah, bh_[1], bh_[3]);
                mma16816(s_[2*np],   ah, bl_[0], bl_[2]);
                mma16816(s_[2*np+1], ah, bl_[1], bl_[3]);
                mma16816(s_[2*np],   al, bh_[0], bh_[2]);
                mma16816(s_[2*np+1], al, bh_[1], bh_[3]);
            }
        }

        int row0 = qt * 128 + warp * 16 + g;
        int row1 = row0 + 8;
        float tm0 = -1e30f, tm1 = -1e30f;
        #pragma unroll
        for (int n = 0; n < 8; n++) {
            int c0 = n * 8 + tg * 2;
            int gc0 = kt * 64 + c0, gc1 = gc0 + 1;
            bool am0 = smask[c0] != 0, am1 = smask[c0 + 1] != 0;
            bool b00 = am0 && (!sliding || abs(row0 - gc0) <= SW);
            bool b01 = am1 && (!sliding || abs(row0 - gc1) <= SW);
            bool b10 = am0 && (!sliding || abs(row1 - gc0) <= SW);
            bool b11 = am1 && (!sliding || abs(row1 - gc1) <= SW);
            s_[n][0] = b00 ? s_[n][0] * ATT_SCALE : -1e30f;
            s_[n][1] = b01 ? s_[n][1] * ATT_SCALE : -1e30f;
            s_[n][2] = b10 ? s_[n][2] * ATT_SCALE : -1e30f;
            s_[n][3] = b11 ? s_[n][3] * ATT_SCALE : -1e30f;
            tm0 = fmaxf(tm0, fmaxf(s_[n][0], s_[n][1]));
            tm1 = fmaxf(tm1, fmaxf(s_[n][2], s_[n][3]));
        }
        tm0 = fmaxf(tm0, __shfl_xor_sync(0xffffffffu, tm0, 1));
        tm0 = fmaxf(tm0, __shfl_xor_sync(0xffffffffu, tm0, 2));
        tm1 = fmaxf(tm1, __shfl_xor_sync(0xffffffffu, tm1, 1));
        tm1 = fmaxf(tm1, __shfl_xor_sync(0xffffffffu, tm1, 2));
        float nm0 = fmaxf(m0, tm0), nm1 = fmaxf(m1, tm1);
        float sf0 = expf(m0 - nm0), sf1 = expf(m1 - nm1);
        m0 = nm0; m1 = nm1;

        float ps0 = 0.f, ps1 = 0.f;
        int pr0 = (warp * 16 + g) * FS_PS;
        int pr1 = (warp * 16 + g + 8) * FS_PS;
        #pragma unroll
        for (int n = 0; n < 8; n++) {
            int c0 = n * 8 + tg * 2;
            float p00 = expf(s_[n][0] - m0), p01 = expf(s_[n][1] - m0);
            float p10 = expf(s_[n][2] - m1), p11 = expf(s_[n][3] - m1);
            ps0 += p00 + p01; ps1 += p10 + p11;
            split_pair(&fsm[SPH + pr0 + c0], &fsm[SPL + pr0 + c0], p00, p01);
            split_pair(&fsm[SPH + pr1 + c0], &fsm[SPL + pr1 + c0], p10, p11);
        }
        ps0 += __shfl_xor_sync(0xffffffffu, ps0, 1);
        ps0 += __shfl_xor_sync(0xffffffffu, ps0, 2);
        ps1 += __shfl_xor_sync(0xffffffffu, ps1, 1);
        ps1 += __shfl_xor_sync(0xffffffffu, ps1, 2);
        l0 = l0 * sf0 + ps0;
        l1 = l1 * sf1 + ps1;
        #pragma unroll
        for (int n = 0; n < 16; n++) {
            o_[n][0] *= sf0; o_[n][1] *= sf0;
            o_[n][2] *= sf1; o_[n][3] *= sf1;
        }
        __syncwarp();

        #pragma unroll
        for (int kc = 0; kc < 4; kc++) {
            uint32_t ph_[4], pl_[4];
            int poff = (warp * 16 + (lane & 15)) * FS_PS + kc * 16 + ((lane >> 4) << 3);
            ldmx4(ph_, &fsm[SPH + poff]);
            ldmx4(pl_, &fsm[SPL + poff]);
            #pragma unroll
            for (int np = 0; np < 8; np++) {
                uint32_t vh_[4], vl_[4];
                int voff = (kc * 16 + (lane & 15)) * FS_KS + np * 16 + ((lane >> 4) << 3);
                ldmx4t(vh_, &fsm[SVH + voff]);
                ldmx4t(vl_, &fsm[SVL + voff]);
                mma16816(o_[2*np],   ph_, vh_[0], vh_[1]);
                mma16816(o_[2*np+1], ph_, vh_[2], vh_[3]);
                mma16816(o_[2*np],   ph_, vl_[0], vl_[1]);
                mma16816(o_[2*np+1], ph_, vl_[2], vl_[3]);
                mma16816(o_[2*np],   pl_, vh_[0], vh_[1]);
                mma16816(o_[2*np+1], pl_, vh_[2], vh_[3]);
            }
        }
        __syncthreads();
    }

    float inv0 = 1.f / l0, inv1 = 1.f / l1;
    long long tok0 = (long long)b * LL + qt * 128 + warp * 16 + g;
    #pragma unroll
    for (int n = 0; n < 16; n++) {
        int col = h * HD + n * 8 + tg * 2;
        long long a0 = tok0 * (NH * HD) + col;
        long long a1 = (tok0 + 8) * (NH * HD) + col;
        split_pair(Ohi + a0, Olo + a0, o_[n][0] * inv0, o_[n][1] * inv0);
        split_pair(Ohi + a1, Olo + a1, o_[n][2] * inv1, o_[n][3] * inv1);
    }
}

// ---------------- split helpers ----------------------------------------------
__global__ void split_k(const float* __restrict__ X,
                        __nv_bfloat16* __restrict__ hi, __nv_bfloat16* __restrict__ lo,
                        long long n) {
    long long i = (long long)blockIdx.x * blockDim.x + threadIdx.x;
    long long stride = (long long)gridDim.x * blockDim.x;
    for (; i < n; i += stride) {
        float v = X[i];
        __nv_bfloat16 h = __float2bfloat16(v);
        hi[i] = h;
        lo[i] = __float2bfloat16(v - __bfloat162float(h));
    }
}

// W [z][K][N] f32 -> hi/lo at obase + z*lsOut + k*ldout + colOff + n
__global__ void split_cols_k(const float* __restrict__ W,
                             __nv_bfloat16* __restrict__ hi, __nv_bfloat16* __restrict__ lo,
                             int K, int N, int ldout, int colOff, long long lsOut) {
    long long z = blockIdx.z;
    const float* src = W + z * (long long)K * N;
    long long ob = z * lsOut;
    long long tot = (long long)K * N;
    long long i = (long long)blockIdx.x * blockDim.x + threadIdx.x;
    long long stride = (long long)gridDim.x * blockDim.x;
    for (; i < tot; i += stride) {
        long long k = i / N;
        int n = (int)(i - k * N);
        float v = src[i];
        __nv_bfloat16 h = __float2bfloat16(v);
        long long o = ob + k * ldout + colOff + n;
        hi[o] = h;
        lo[o] = __float2bfloat16(v - __bfloat162float(h));
    }
}

// ---------------- RMSNorm variants ------------------------------------------
__global__ void rmsnorm_k(const float* __restrict__ X, const float* __restrict__ w,
                          float* __restrict__ Y, int D) {
    long long row = blockIdx.x;
    const float* x = X + row * D;
    float* y = Y + row * D;
    float ss = 0.f;
    for (int j = threadIdx.x; j < D; j += blockDim.x) { float v = x[j]; ss += v * v; }
    float tot = blk_sum(ss);
    float r = rsqrtf(tot / (float)D + EPSF);
    for (int j = threadIdx.x; j < D; j += blockDim.x) y[j] = w[j] * x[j] * r;
}

__global__ void rmsnorm_split_k(const float* __restrict__ X, const float* __restrict__ w,
                                __nv_bfloat16* __restrict__ hi, __nv_bfloat16* __restrict__ lo,
                                int D) {
    long long row = blockIdx.x;
    const float* x = X + row * D;
    float ss = 0.f;
    for (int j = threadIdx.x; j < D; j += blockDim.x) { float v = x[j]; ss += v * v; }
    float tot = blk_sum(ss);
    float r = rsqrtf(tot / (float)D + EPSF);
    for (int j = threadIdx.x; j < D; j += blockDim.x) {
        float v = w[j] * x[j] * r;
        __nv_bfloat16 h = __float2bfloat16(v);
        hi[row * D + j] = h;
        lo[row * D + j] = __float2bfloat16(v - __bfloat162float(h));
    }
}

// ---------------- RoPE table -------------------------------------------------
__global__ void rope_table_k() {
    int pos = blockIdx.x;
    int d = threadIdx.x;
    int j = d & 63;
    double inv = exp2(-(double)j * (19.931568569324174 / 64.0));
    double ang = (double)pos * inv;
    g_cos[pos * HD + d] = (float)cos(ang);
    g_sin[pos * HD + d] = (float)sin(ang);
}

// ---------------- per-head RMSNorm + RoPE (reads fused g_qkv) ----------------
__global__ void qknorm_rope_k(const float* __restrict__ wq, const float* __restrict__ wk) {
    int tok = blockIdx.x;
    int head = blockIdx.y;       // 0..NH+NKV-1
    int d = threadIdx.x;
    const float* w;
    long long src, dst;
    if (head < NH) {
        src = (long long)tok * 4096 + head * HD + d;
        dst = ((long long)tok * NH + head) * HD + d;
        w = wq;
    } else {
        int kvh = head - NH;
        src = (long long)tok * 4096 + 2048 + kvh * HD + d;
        dst = ((long long)tok * NKV + kvh) * HD + d;
        w = wk;
    }

    float v = g_qkv[src];
    float ss = v * v;
    #pragma unroll
    for (int o = 16; o; o >>= 1) ss += __shfl_xor_sync(0xffffffffu, ss, o);
    __shared__ float wsum[4];
    __shared__ float smv[HD];
    if ((d & 31) == 0) wsum[d >> 5] = ss;
    __syncthreads();
    float tot = wsum[0] + wsum[1] + wsum[2] + wsum[3];
    float r = rsqrtf(tot / (float)HD + EPSF);
    float xn = w[d] * v * r;
    smv[d] = xn;
    __syncthreads();
    int pos = tok & (LL - 1);
    float c = g_cos[pos * HD + d];
    float s = g_sin[pos * HD + d];
    float rot = (d < 64) ? -smv[d + 64] : smv[d - 64];
    float fin = xn * c + rot * s;
    __nv_bfloat16 hi = __float2bfloat16(fin);
    __nv_bfloat16 lo = __float2bfloat16(fin - __bfloat162float(hi));
    if (head < NH) { g_qh[dst] = hi; g_ql[dst] = lo; }
    else           { g_kh[dst] = hi; g_kl[dst] = lo; }
}

// ---------------- V split (from fused g_qkv) ---------------------------------
__global__ void split_v_k() {
    long long n = (long long)NTOK * NKV * HD;
    long long i = (long long)blockIdx.x * blockDim.x + threadIdx.x;
    long long stride = (long long)gridDim.x * blockDim.x;
    for (; i < n; i += stride) {
        long long tok = i >> 10;
        int c = (int)(i & 1023);
        float v = g_qkv[tok * 4096 + 3072 + c];
        __nv_bfloat16 h = __float2bfloat16(v);
        g_vh[i] = h;
        g_vl[i] = __float2bfloat16(v - __bfloat162float(h));
    }
}

// ---------------- SiLU(g)*u (fused g_gu) -> bf16 split -----------------------
__global__ void silu_mul_split_k() {
    long long n = (long long)NTOK * INTD;
    long long i = (long long)blockIdx.x * blockDim.x + threadIdx.x;
    long long stride = (long long)gridDim.x * blockDim.x;
    for (; i < n; i += stride) {
        long long r = i / INTD;
        int c = (int)(i - r * INTD);
        float x = g_gu[r * (2 * INTD) + c];
        float u = g_gu[r * (2 * INTD) + INTD + c];
        float s = x / (1.0f + expf(-x));
        float v = s * u;
        __nv_bfloat16 h = __float2bfloat16(v);
        g_act_hi[i] = h;
        g_act_lo[i] = __float2bfloat16(v - __bfloat162float(h));
    }
}

// ---------------- host orchestration ----------------------------------------
extern "C" void kernel_launch(void* const* d_in, const int* in_sizes, int n_in,
                              void* d_out, int out_size) {
    (void)in_sizes; (void)n_in; (void)out_size;
    const float* x       = (const float*)d_in[0];
    const int*   amask   = (const int*)  d_in[1];
    const float* W_embed = (const float*)d_in[2];
    const float* b_embed = (const float*)d_in[3];
    const float* Wq      = (const float*)d_in[4];
    const float* Wk      = (const float*)d_in[5];
    const float* Wv      = (const float*)d_in[6];
    const float* Wo      = (const float*)d_in[7];
    const float* w_in    = (const float*)d_in[8];
    const float* w_post  = (const float*)d_in[9];
    const float* w_qn    = (const float*)d_in[10];
    const float* w_kn    = (const float*)d_in[11];
    const float* Wg      = (const float*)d_in[12];
    const float* Wu      = (const float*)d_in[13];
    const float* Wd      = (const float*)d_in[14];
    const float* w_final = (const float*)d_in[15];

    float *h, *qkv, *gu;
    cudaGetSymbolAddress((void**)&h,   g_h);
    cudaGetSymbolAddress((void**)&qkv, g_qkv);
    cudaGetSymbolAddress((void**)&gu,  g_gu);
    __nv_bfloat16 *whi, *wlo, *hnh, *hnl, *ach, *acl;
    cudaGetSymbolAddress((void**)&whi, g_whi);
    cudaGetSymbolAddress((void**)&wlo, g_wlo);
    cudaGetSymbolAddress((void**)&hnh, g_hn_hi);
    cudaGetSymbolAddress((void**)&hnl, g_hn_lo);
    cudaGetSymbolAddress((void**)&ach, g_act_hi);
    cudaGetSymbolAddress((void**)&acl, g_act_lo);
    __nv_bfloat16 *qh, *ql, *kh, *kl, *vh, *vl;
    cudaGetSymbolAddress((void**)&qh, g_qh);
    cudaGetSymbolAddress((void**)&ql, g_ql);
    cudaGetSymbolAddress((void**)&kh, g_kh);
    cudaGetSymbolAddress((void**)&kl, g_kl);
    cudaGetSymbolAddress((void**)&vh, g_vh);
    cudaGetSymbolAddress((void**)&vl, g_vl);

    cudaFuncSetAttribute(gemm_bf3<false,false>, cudaFuncAttributeMaxDynamicSharedMemorySize, GEMM_SMEM_BYTES);
    cudaFuncSetAttribute(gemm_bf3<true,false>,  cudaFuncAttributeMaxDynamicSharedMemorySize, GEMM_SMEM_BYTES);
    cudaFuncSetAttribute(gemm_bf3<false,true>,  cudaFuncAttributeMaxDynamicSharedMemorySize, GEMM_SMEM_BYTES);
    cudaFuncSetAttribute(flash_attn_k, cudaFuncAttributeMaxDynamicSharedMemorySize, FLASH_SMEM_BYTES);

    const int SB = 256, SG = 1184;
    // Launch order: #6 (ncu -s 5 -c 1) = embed gemm_bf3.
    split_k<<<SG, SB>>>(x, hnh, hnl, (long long)NTOK * TXT);                                  // 1
    split_cols_k<<<dim3(SG, 1, 1), SB>>>(W_embed, whi + OFF_EMB, wlo + OFF_EMB,
                                         TXT, HID, HID, 0, 0);                               // 2
    split_cols_k<<<dim3(296, 1, NLAYERS), SB>>>(Wq, whi + OFF_QKV, wlo + OFF_QKV,
                                         HID, NH*HD, 4096, 0, 2048LL*4096);                  // 3
    split_cols_k<<<dim3(296, 1, NLAYERS), SB>>>(Wk, whi + OFF_QKV, wlo + OFF_QKV,
                                         HID, NKV*HD, 4096, 2048, 2048LL*4096);              // 4
    split_cols_k<<<dim3(296, 1, NLAYERS), SB>>>(Wv, whi + OFF_QKV, wlo + OFF_QKV,
                                         HID, NKV*HD, 4096, 3072, 2048LL*4096);              // 5
    gemm_bf3<false,true><<<dim3(HID/GBN, NTOK/GBM), 256, GEMM_SMEM_BYTES>>>(                  // 6 (profiled)
        hnh, hnl, whi + OFF_EMB, wlo + OFF_EMB, b_embed, h, TXT, TXT, HID, HID);
    split_cols_k<<<dim3(296, 1, NLAYERS), SB>>>(Wo, whi + OFF_WO, wlo + OFF_WO,
                                         NH*HD, HID, HID, 0, 2048LL*2048);
    split_cols_k<<<dim3(296, 1, NLAYERS), SB>>>(Wg, whi + OFF_GU, wlo + OFF_GU,
                                         HID, INTD, 2*INTD, 0, 2048LL*12288);
    split_cols_k<<<dim3(296, 1, NLAYERS), SB>>>(Wu, whi + OFF_GU, wlo + OFF_GU,
                                         HID, INTD, 2*INTD, INTD, 2048LL*12288);
    split_cols_k<<<dim3(296, 1, NLAYERS), SB>>>(Wd, whi + OFF_WD, wlo + OFF_WD,
                                         INTD, HID, HID, 0, 6144LL*2048);
    rope_table_k<<<LL, HD>>>();

    for (int i = 0; i < NLAYERS; i++) {
        rmsnorm_split_k<<<NTOK, 256>>>(h, w_in + (long long)i * HID, hnh, hnl, HID);

        // fused QKV [2048 -> 4096]
        gemm_bf3<false,false><<<dim3(4096/GBN, NTOK/GBM), 256, GEMM_SMEM_BYTES>>>(
            hnh, hnl, whi + OFF_QKV + (long long)i * 2048 * 4096,
            wlo + OFF_QKV + (long long)i * 2048 * 4096, nullptr, qkv, HID, HID, 4096, 4096);

        qknorm_rope_k<<<dim3(NTOK, NH + NKV), HD>>>(
            w_qn + (long long)i * HD, w_kn + (long long)i * HD);
        split_v_k<<<SG, SB>>>();

        flash_attn_k<<<dim3(8, NH, BB), 256, FLASH_SMEM_BYTES>>>(
            qh, ql, kh, kl, vh, vl, amask, ach, acl, (i % 2 == 0) ? 1 : 0);

        // h += attn @ Wo
        gemm_bf3<true,false><<<dim3(HID/GBN, NTOK/GBM), 256, GEMM_SMEM_BYTES>>>(
            ach, acl, whi + OFF_WO + (long long)i * 2048 * 2048,
            wlo + OFF_WO + (long long)i * 2048 * 2048, nullptr, h, NH*HD, NH*HD, HID, HID);

        rmsnorm_split_k<<<NTOK, 256>>>(h, w_post + (long long)i * HID, hnh, hnl, HID);

        // fused gate|up [2048 -> 12288]
        gemm_bf3<false,false><<<dim3(12288/GBN, NTOK/GBM), 256, GEMM_SMEM_BYTES>>>(
            hnh, hnl, whi + OFF_GU + (long long)i * 2048 * 12288,
            wlo + OFF_GU + (long long)i * 2048 * 12288, nullptr, gu, HID, HID, 2*INTD, 2*INTD);

        silu_mul_split_k<<<SG, SB>>>();

        // h += act @ Wd
        gemm_bf3<true,false><<<dim3(HID/GBN, NTOK/GBM), 256, GEMM_SMEM_BYTES>>>(
            ach, acl, whi + OFF_WD + (long long)i * 6144 * 2048,
            wlo + OFF_WD + (long long)i * 6144 * 2048, nullptr, h, INTD, INTD, HID, HID);
    }

    rmsnorm_k<<<NTOK, 256>>>(h, w_final, (float*)d_out, HID);
}